// round 11
// baseline (speedup 1.0000x reference)
#include <cuda_runtime.h>
#include <cuda_bf16.h>
#include <math.h>
#include <stdint.h>

#define BSZ  128
#define NDIM 256
#define HDIM 1024
#define ALPHA 60.0f
#define BETA  20.0f
#define EPSC  1e-8f

typedef unsigned int uint;

// ---------------- scratch (allocation-free __device__ globals) ----------------
__device__ __align__(16) __nv_bfloat16 g_xh[BSZ * NDIM],    g_xl[BSZ * NDIM];
__device__ __align__(16) __nv_bfloat16 g_Hh[3][BSZ * HDIM], g_Hl[3][BSZ * HDIM];
__device__ __align__(16) float         g_fgk[3][BSZ * NDIM];
__device__ __align__(16) float         g_P2p[3][8][BSZ * NDIM];
__device__ float g_F1p[32], g_F2p[32];
__device__ int   g_bad[BSZ];

// fallback-only scratch
__device__ __align__(16) __nv_bfloat16 g_K2Th[HDIM * NDIM],  g_K2Tl[HDIM * NDIM];
__device__ __align__(16) __nv_bfloat16 g_K1Th[NDIM * HDIM],  g_K1Tl[NDIM * HDIM];
__device__ __align__(16) float         g_D[BSZ * HDIM];
__device__ __align__(16) __nv_bfloat16 g_fgh[2][BSZ * NDIM], g_fgl[2][BSZ * NDIM];
__device__ __align__(16) __nv_bfloat16 g_dvh[2][BSZ * HDIM], g_dvl[2][BSZ * HDIM];
__device__ __align__(16) float         g_P3p[2][2][BSZ * HDIM];
__device__ __align__(16) float         g_P4p[2][8][BSZ * NDIM];

// ---------------- grid barrier ----------------
__device__ int g_cnt = 0, g_sense = 0;
__device__ __forceinline__ void gbar()
{
    __threadfence();
    __syncthreads();
    if (threadIdx.x == 0) {
        int s = *(volatile int*)&g_sense;
        int old = atomicAdd(&g_cnt, 1);
        if (old == (int)gridDim.x - 1) {
            atomicExch(&g_cnt, 0);
            __threadfence();
            atomicExch(&g_sense, 1 - s);
        } else {
            while (*(volatile int*)&g_sense == s) __nanosleep(64);
        }
        __threadfence();
    }
    __syncthreads();
}

// ---------------- helpers ----------------
__device__ __forceinline__ uint smem_u32(const void* p)
{
    uint a;
    asm("{ .reg .u64 t; cvta.to.shared.u64 t, %1; cvt.u32.u64 %0, t; }"
        : "=r"(a) : "l"(p));
    return a;
}
__device__ __forceinline__ void split_bf16(float v, __nv_bfloat16& h, __nv_bfloat16& l)
{
    h = __float2bfloat16(v);
    l = __float2bfloat16(v - __bfloat162float(h));
}
__device__ __forceinline__ void st_bf2(__nv_bfloat16* p, __nv_bfloat16 a, __nv_bfloat16 b)
{
    __nv_bfloat162 t; t.x = a; t.y = b;
    *reinterpret_cast<__nv_bfloat162*>(p) = t;
}
__device__ __forceinline__ uint pack2(__nv_bfloat16 a, __nv_bfloat16 b)
{
    __nv_bfloat162 t; t.x = a; t.y = b;
    return *reinterpret_cast<uint*>(&t);
}
__device__ __forceinline__ void split4(float4 v, uint2& hu, uint2& lu)
{
    __nv_bfloat16 h0, l0, h1, l1, h2, l2, h3, l3;
    split_bf16(v.x, h0, l0); split_bf16(v.y, h1, l1);
    split_bf16(v.z, h2, l2); split_bf16(v.w, h3, l3);
    hu.x = pack2(h0, h1); hu.y = pack2(h2, h3);
    lu.x = pack2(l0, l1); lu.y = pack2(l2, l3);
}
__device__ __forceinline__ float frcp(float x)
{
    float r;
    asm("rcp.approx.f32 %0, %1;" : "=f"(r) : "f"(x));
    return r;
}
__device__ __forceinline__ float ftanh(float x)
{
    float ax = fabsf(x);
    float e = __expf(ax + ax);
    float t = 1.0f - 2.0f * frcp(e + 1.0f);
    return copysignf(t, x);
}

#define CP16(dst, src) \
    asm volatile("cp.async.cg.shared.global [%0], [%1], 16;" :: "r"(dst), "l"(src))
#define CP_COMMIT() asm volatile("cp.async.commit_group;" ::: "memory")
#define CP_WAIT(n)  asm volatile("cp.async.wait_group %0;" :: "n"(n) : "memory")

#define LDM4(r, addr) \
    asm volatile("ldmatrix.sync.aligned.m8n8.x4.shared.b16 {%0,%1,%2,%3}, [%4];" \
        : "=r"((r)[0]), "=r"((r)[1]), "=r"((r)[2]), "=r"((r)[3]) : "r"(addr))

#define MMA16816(c, a, b0, b1) \
    asm volatile("mma.sync.aligned.m16n8k16.row.col.f32.bf16.bf16.f32 " \
        "{%0,%1,%2,%3}, {%4,%5,%6,%7}, {%8,%9}, {%0,%1,%2,%3};" \
        : "+f"((c)[0]), "+f"((c)[1]), "+f"((c)[2]), "+f"((c)[3]) \
        : "r"((a)[0]), "r"((a)[1]), "r"((a)[2]), "r"((a)[3]), "r"(b0), "r"(b1))

// ---------------- smem layouts ----------------
// fallback buffers (round-9/10 verified)
#define BUF_AL 16384
#define BUF_BH 32768
#define BUF_BL 40960
#define BUF_SZ 49152
#define SMEM_TOTAL (2 * BUF_SZ)
// P1 buffer (64xK64 A h/l + 32xK64 B h/l): 8K+8K+4K+4K = 24K
#define P1_AL 8192
#define P1_BH 16384
#define P1_BL 20480
#define P1_STRIDE 24576
// P2 buffer (64xK64 A h/l + 64xK64 B h/l): 8K+8K+8K+8K = 32K
#define P2_AL 8192
#define P2_BH 16384
#define P2_BL 24576
#define P2_STRIDE 32768

// ============================================================
// compute_m64<NJG>: 64 x (NJG*32) tile, one K=64 chunk.
// 8 warps: 4m x 2n; warp tile 16 x (NJG*16).
// acc[NJG*2][4].
// ============================================================
template <int NJG>
__device__ __forceinline__ void compute_m64(uint buf, uint al_off, uint bh_off,
                                            uint bl_off, float acc[][4])
{
    const int lane = threadIdx.x & 31;
    const int w = threadIdx.x >> 5;
    const int m0w = (w & 3) * 16;
    const int n0w = (w >> 2) * (NJG * 16);
    const int arow = m0w + (lane & 15);
    const int au_l = lane >> 4;
    const int brow_l = (lane & 7) + ((lane >> 4) & 1) * 8;
    const int bu_l = (lane >> 3) & 1;

#pragma unroll
    for (int ks = 0; ks < 4; ks++) {
        uint ah[4], al[4], bh[NJG][4], bl[NJG][4];
        {
            const int u = ks * 2 + au_l;
            const uint ad = buf + (uint)arow * 128 + (uint)((u ^ (arow & 7)) * 16);
            LDM4(ah, ad);
            LDM4(al, ad + al_off);
        }
#pragma unroll
        for (int njp = 0; njp < NJG; njp++) {
            const int r = n0w + njp * 16 + brow_l;
            const int u = ks * 2 + bu_l;
            const uint bd = buf + bh_off + (uint)r * 128 + (uint)((u ^ (r & 7)) * 16);
            LDM4(bh[njp], bd);
            LDM4(bl[njp], bd + (bl_off - bh_off));
        }
#pragma unroll
        for (int njp = 0; njp < NJG; njp++)
#pragma unroll
            for (int h = 0; h < 2; h++) {
                float* c = acc[njp * 2 + h];
                MMA16816(c, ah, bh[njp][2 * h], bh[njp][2 * h + 1]);
                MMA16816(c, ah, bl[njp][2 * h], bl[njp][2 * h + 1]);
                MMA16816(c, al, bh[njp][2 * h], bh[njp][2 * h + 1]);
            }
    }
}

// ============================================================
// P1 unit: H[z][mh*64.., n*32..+32] = tanh(xslice @ W1rows^T + b1)
// A (x bf16) via cp.async, B (W1 fp32, 32 rows) via LDG+split+STS.
// K=256 -> 4 chunks of 64, pipelined.
// ============================================================
__device__ void p1_unit(char* smem, uint sb, int z, int mh, int n,
                        const float* __restrict__ W1full,
                        const float* __restrict__ b1)
{
    const int tid = threadIdx.x;
    const int lane = tid & 31, w = tid >> 5;
    const float* W = W1full + (size_t)n * 32 * NDIM;
    const __nv_bfloat16* Ah = g_xh + (size_t)mh * 64 * NDIM;
    const __nv_bfloat16* Al = g_xl + (size_t)mh * 64 * NDIM;
    const uint bufs[2] = {sb, sb + P1_STRIDE};
    char* cbuf[2] = {smem, smem + P1_STRIDE};

    float4 bw[2];
    auto ldgB = [&](int kc) {
#pragma unroll
        for (int i = 0; i < 2; i++) {
            const int idx = i * 256 + tid;
            bw[i] = *reinterpret_cast<const float4*>(
                &W[(size_t)(idx >> 4) * NDIM + kc + (idx & 15) * 4]);
        }
    };
    auto stsB = [&](char* b) {
#pragma unroll
        for (int i = 0; i < 2; i++) {
            const int idx = i * 256 + tid;
            const int row = idx >> 4;
            const int u = (idx & 15) >> 1, h8 = (idx & 1) * 8;
            const uint off = (uint)row * 128 + (uint)((u ^ (row & 7)) * 16) + h8;
            uint2 hu, lu; split4(bw[i], hu, lu);
            *reinterpret_cast<uint2*>(b + P1_BH + off) = hu;
            *reinterpret_cast<uint2*>(b + P1_BL + off) = lu;
        }
    };
    auto cpA = [&](uint b, int kc) {
#pragma unroll
        for (int i = 0; i < 2; i++) {
            const int idx = i * 256 + tid;
            const int row = idx >> 3, u = idx & 7;
            const uint off = (uint)row * 128 + (uint)((u ^ (row & 7)) * 16);
            CP16(b + off,          Ah + (size_t)row * NDIM + kc + u * 8);
            CP16(b + P1_AL + off,  Al + (size_t)row * NDIM + kc + u * 8);
        }
        CP_COMMIT();
    };

    float acc[2][4];
#pragma unroll
    for (int a = 0; a < 2; a++)
#pragma unroll
        for (int q = 0; q < 4; q++) acc[a][q] = 0.f;

    ldgB(0);
    cpA(bufs[0], 0);
    cpA(bufs[1], 64);
    stsB(cbuf[0]);
    ldgB(64);
    CP_WAIT(1);
    __syncthreads();
#pragma unroll
    for (int c = 0; c < 4; c++) {
        compute_m64<1>(bufs[c & 1], P1_AL, P1_BH, P1_BL, acc);
        if (c < 3) {
            __syncthreads();
            stsB(cbuf[(c + 1) & 1]);
            if (c < 2) {
                cpA(bufs[c & 1], (c + 2) * 64);
                ldgB((c + 2) * 64);
                CP_WAIT(1);
            } else {
                CP_WAIT(0);
            }
            __syncthreads();
        }
    }

    // epilogue: tanh + hi/lo split
    const int g = lane >> 2, t4 = lane & 3;
    const int m0w = (w & 3) * 16, n0w = (w >> 2) * 16;
    const int row = mh * 64 + m0w + g;
#pragma unroll
    for (int j = 0; j < 2; j++) {
        const int col = n * 32 + n0w + j * 8 + t4 * 2;
        float h0 = ftanh(acc[j][0] + b1[col]);
        float h1 = ftanh(acc[j][1] + b1[col + 1]);
        __nv_bfloat16 p0, q0, p1, q1;
        split_bf16(h0, p0, q0); split_bf16(h1, p1, q1);
        st_bf2(&g_Hh[z][(size_t)row * HDIM + col], p0, p1);
        st_bf2(&g_Hl[z][(size_t)row * HDIM + col], q0, q1);
        float h2 = ftanh(acc[j][2] + b1[col]);
        float h3 = ftanh(acc[j][3] + b1[col + 1]);
        split_bf16(h2, p0, q0); split_bf16(h3, p1, q1);
        st_bf2(&g_Hh[z][(size_t)(row + 8) * HDIM + col], p0, p1);
        st_bf2(&g_Hl[z][(size_t)(row + 8) * HDIM + col], q0, q1);
    }
}

// ============================================================
// P2 unit: P2p[z][s][mh*64.., n*64..] = H[z] chunk @ W2[z] rows^T
// A (H bf16) via cp.async, B (W2 fp32, 64 rows) via LDG+split.
// K=128 -> 2 chunks of 64.
// ============================================================
__device__ void p2_unit(char* smem, uint sb, int z, int mh, int n, int s,
                        const float* __restrict__ W2full)
{
    const int tid = threadIdx.x;
    const int lane = tid & 31, w = tid >> 5;
    const int k0 = s * 128;
    const __nv_bfloat16* Ah = g_Hh[z] + (size_t)mh * 64 * HDIM;
    const __nv_bfloat16* Al = g_Hl[z] + (size_t)mh * 64 * HDIM;
    const float* W = W2full + (size_t)n * 64 * HDIM;
    const uint bufs[2] = {sb, sb + P2_STRIDE};
    char* cbuf[2] = {smem, smem + P2_STRIDE};

    float4 bw[4];
    auto ldgB = [&](int kc) {
#pragma unroll
        for (int i = 0; i < 4; i++) {
            const int idx = i * 256 + tid;
            bw[i] = *reinterpret_cast<const float4*>(
                &W[(size_t)(idx >> 4) * HDIM + kc + (idx & 15) * 4]);
        }
    };
    auto stsB = [&](char* b) {
#pragma unroll
        for (int i = 0; i < 4; i++) {
            const int idx = i * 256 + tid;
            const int row = idx >> 4;
            const int u = (idx & 15) >> 1, h8 = (idx & 1) * 8;
            const uint off = (uint)row * 128 + (uint)((u ^ (row & 7)) * 16) + h8;
            uint2 hu, lu; split4(bw[i], hu, lu);
            *reinterpret_cast<uint2*>(b + P2_BH + off) = hu;
            *reinterpret_cast<uint2*>(b + P2_BL + off) = lu;
        }
    };
    auto cpA = [&](uint b, int kc) {
#pragma unroll
        for (int i = 0; i < 2; i++) {
            const int idx = i * 256 + tid;
            const int row = idx >> 3, u = idx & 7;
            const uint off = (uint)row * 128 + (uint)((u ^ (row & 7)) * 16);
            CP16(b + off,         Ah + (size_t)row * HDIM + kc + u * 8);
            CP16(b + P2_AL + off, Al + (size_t)row * HDIM + kc + u * 8);
        }
        CP_COMMIT();
    };

    float acc[4][4];
#pragma unroll
    for (int a = 0; a < 4; a++)
#pragma unroll
        for (int q = 0; q < 4; q++) acc[a][q] = 0.f;

    ldgB(k0);
    cpA(bufs[0], k0);
    cpA(bufs[1], k0 + 64);
    stsB(cbuf[0]);
    ldgB(k0 + 64);
    CP_WAIT(1);
    __syncthreads();
    compute_m64<2>(bufs[0], P2_AL, P2_BH, P2_BL, acc);
    __syncthreads();
    stsB(cbuf[1]);
    CP_WAIT(0);
    __syncthreads();
    compute_m64<2>(bufs[1], P2_AL, P2_BH, P2_BL, acc);

    // store fp32 partial
    float* O = g_P2p[z][s];
    const int g = lane >> 2, t4 = lane & 3;
    const int m0w = (w & 3) * 16, n0w = (w >> 2) * 32;
    const int row = mh * 64 + m0w + g;
#pragma unroll
    for (int njp = 0; njp < 2; njp++)
#pragma unroll
        for (int h = 0; h < 2; h++) {
            const int j = njp * 2 + h;
            const int col = n * 64 + n0w + njp * 16 + h * 8 + t4 * 2;
            *reinterpret_cast<float2*>(&O[(size_t)row * NDIM + col]) =
                make_float2(acc[j][0], acc[j][1]);
            *reinterpret_cast<float2*>(&O[(size_t)(row + 8) * NDIM + col]) =
                make_float2(acc[j][2], acc[j][3]);
        }
}

// ================= fallback machinery (verified; certified-unused) =============
__device__ __forceinline__ void compute64(uint buf, float acc[2][4][4])
{
    const int lane = threadIdx.x & 31;
    const int w = threadIdx.x >> 5;
    const int m0w = (w & 3) * 32;
    const int n0w = (w >> 2) * 32;
    const int arow_l = lane & 15;
    const int au_l   = lane >> 4;
    const int brow_l = (lane & 7) + ((lane >> 4) & 1) * 8;
    const int bu_l   = (lane >> 3) & 1;
#pragma unroll
    for (int ks = 0; ks < 4; ks++) {
        uint ah[2][4], al[2][4], bh[2][4], bl[2][4];
#pragma unroll
        for (int mi = 0; mi < 2; mi++) {
            const int r = m0w + mi * 16 + arow_l;
            const int u = ks * 2 + au_l;
            const uint ad = buf + (uint)r * 128 + (uint)((u ^ (r & 7)) * 16);
            LDM4(ah[mi], ad);
            LDM4(al[mi], ad + BUF_AL);
        }
#pragma unroll
        for (int njp = 0; njp < 2; njp++) {
            const int r = n0w + njp * 16 + brow_l;
            const int u = ks * 2 + bu_l;
            const uint bd = buf + BUF_BH + (uint)r * 128 + (uint)((u ^ (r & 7)) * 16);
            LDM4(bh[njp], bd);
            LDM4(bl[njp], bd + (BUF_BL - BUF_BH));
        }
#pragma unroll
        for (int mi = 0; mi < 2; mi++)
#pragma unroll
            for (int njp = 0; njp < 2; njp++)
#pragma unroll
                for (int h = 0; h < 2; h++) {
                    float* c = acc[mi][njp * 2 + h];
                    MMA16816(c, ah[mi], bh[njp][2 * h], bh[njp][2 * h + 1]);
                    MMA16816(c, ah[mi], bl[njp][2 * h], bl[njp][2 * h + 1]);
                    MMA16816(c, al[mi], bh[njp][2 * h], bh[njp][2 * h + 1]);
                }
    }
}
struct Job {
    const __nv_bfloat16 *Ah, *Al, *Bh, *Bl;
    int lda, ldb, k0, nch, ldo;
    float* Of;
};
__device__ __forceinline__ void fill_chunk(uint buf, const Job& j, int kc)
{
    const int tid = threadIdx.x;
#pragma unroll
    for (int i = 0; i < 4; i++) {
        const int idx = tid + i * 256;
        const int row = idx >> 3, u = idx & 7;
        const uint sw = (uint)row * 128 + (uint)((u ^ (row & 7)) * 16);
        const size_t go = (size_t)row * j.lda + kc + u * 8;
        CP16(buf + sw,          j.Ah + go);
        CP16(buf + BUF_AL + sw, j.Al + go);
    }
#pragma unroll
    for (int i = 0; i < 2; i++) {
        const int idx = tid + i * 256;
        const int row = idx >> 3, u = idx & 7;
        const uint sw = (uint)row * 128 + (uint)((u ^ (row & 7)) * 16);
        const size_t go = (size_t)row * j.ldb + kc + u * 8;
        CP16(buf + BUF_BH + sw, j.Bh + go);
        CP16(buf + BUF_BL + sw, j.Bl + go);
    }
    CP_COMMIT();
}
__device__ __forceinline__ void store_tile(const Job& j, const float acc[2][4][4])
{
    const int lane = threadIdx.x & 31;
    const int w = threadIdx.x >> 5;
    const int g = lane >> 2, t = lane & 3;
    const int m0w = (w & 3) * 32, n0w = (w >> 2) * 32;
#pragma unroll
    for (int mi = 0; mi < 2; mi++)
#pragma unroll
        for (int nj = 0; nj < 4; nj++) {
            const int r = m0w + mi * 16 + g, c = n0w + nj * 8 + t * 2;
            *reinterpret_cast<float2*>(&j.Of[(size_t)r * j.ldo + c]) =
                make_float2(acc[mi][nj][0], acc[mi][nj][1]);
            *reinterpret_cast<float2*>(&j.Of[(size_t)(r + 8) * j.ldo + c]) =
                make_float2(acc[mi][nj][2], acc[mi][nj][3]);
        }
}
template <class DEC>
__device__ void gemm_phase(uint sb, int U, const DEC& dec)
{
    const uint buf0 = sb, buf1 = sb + BUF_SZ;
    for (int u = blockIdx.x; u < U; u += gridDim.x) {
        Job j; dec(u, j);
        fill_chunk(buf0, j, j.k0);
        fill_chunk(buf1, j, j.k0 + 64);
        float acc[2][4][4];
#pragma unroll
        for (int a = 0; a < 2; a++)
#pragma unroll
            for (int b = 0; b < 4; b++)
#pragma unroll
                for (int q = 0; q < 4; q++) acc[a][b][q] = 0.f;
        for (int c = 0; c < j.nch; c++) {
            if (c == j.nch - 1) { CP_WAIT(0); } else { CP_WAIT(1); }
            __syncthreads();
            compute64((c & 1) ? buf1 : buf0, acc);
            __syncthreads();
            if (c + 2 < j.nch)
                fill_chunk((c & 1) ? buf1 : buf0, j, j.k0 + (c + 2) * 64);
        }
        store_tile(j, acc);
        __syncthreads();
    }
}
struct DecP3 {
    __device__ void operator()(int u, Job& j) const {
        const int z = u >> 5, r = u & 31, n = r >> 1, s = r & 1;
        j.Ah = g_fgh[z]; j.Al = g_fgl[z]; j.lda = NDIM;
        j.Bh = g_K2Th + (size_t)n * 64 * NDIM;
        j.Bl = g_K2Tl + (size_t)n * 64 * NDIM; j.ldb = NDIM;
        j.k0 = s * 128; j.nch = 2;
        j.Of = g_P3p[z][s] + n * 64; j.ldo = HDIM;
    }
};
struct DecP4 {
    __device__ void operator()(int u, Job& j) const {
        const int z = u >> 5, r = u & 31, n = r >> 3, s = r & 7;
        j.Ah = g_dvh[z]; j.Al = g_dvl[z]; j.lda = HDIM;
        j.Bh = g_K1Th + (size_t)n * 64 * HDIM;
        j.Bl = g_K1Tl + (size_t)n * 64 * HDIM; j.ldb = HDIM;
        j.k0 = s * 128; j.nch = 2;
        j.Of = g_P4p[z][s] + n * 64; j.ldo = NDIM;
    }
};
__device__ void fnorm_block(const float* __restrict__ W, float* slot, float* red)
{
    float s = 0.f;
    for (int i = threadIdx.x; i < 2048; i += 256) {
        float4 v = reinterpret_cast<const float4*>(W)[i];
        s += v.x * v.x + v.y * v.y + v.z * v.z + v.w * v.w;
    }
#pragma unroll
    for (int off = 16; off > 0; off >>= 1) s += __shfl_down_sync(0xffffffffu, s, off);
    const int warp = threadIdx.x >> 5, lane = threadIdx.x & 31;
    if (lane == 0) red[warp] = s;
    __syncthreads();
    if (threadIdx.x == 0) {
        float t = 0.f;
#pragma unroll
        for (int ww = 0; ww < 8; ww++) t += red[ww];
        *slot = t;
    }
    __syncthreads();
}
__device__ void trans_tile(float (*ts)[65], const float* __restrict__ src, int lds,
                           int r0, int c0, __nv_bfloat16* dh, __nv_bfloat16* dl, int ldd)
{
    const int tid = threadIdx.x;
    __syncthreads();
    for (int i = tid; i < 4096; i += 256) {
        const int r = i >> 6, c = i & 63;
        ts[r][c] = src[(size_t)(r0 + r) * lds + c0 + c];
    }
    __syncthreads();
    for (int i = tid; i < 4096; i += 256) {
        const int dr = i >> 6, dc = i & 63;
        __nv_bfloat16 h, l;
        split_bf16(ts[dc][dr], h, l);
        dh[(size_t)(c0 + dr) * ldd + r0 + dc] = h;
        dl[(size_t)(c0 + dr) * ldd + r0 + dc] = l;
    }
}

// ---------------- persistent fused kernel ----------------
__global__ __launch_bounds__(256, 2) void fused_v3_kernel(
    const float* __restrict__ x,
    const float* __restrict__ Wf1, const float* __restrict__ bf1,
    const float* __restrict__ Wf2, const float* __restrict__ bf2,
    const float* __restrict__ Wg1, const float* __restrict__ bg1,
    const float* __restrict__ Wg2, const float* __restrict__ bg2,
    const float* __restrict__ Wk1, const float* __restrict__ bk1,
    const float* __restrict__ Wk2, const float* __restrict__ bk2,
    float* __restrict__ out)
{
    extern __shared__ char smem[];
    const uint sb = smem_u32(smem);
    float* red = reinterpret_cast<float*>(smem);
    const int tid = threadIdx.x;
    const int bid = blockIdx.x;
    const int gtid = bid * 256 + tid;
    const int gsz = gridDim.x * 256;

    // ---------- PhPre: convert x (tiny) + Frobenius norms ----------
    for (int i = gtid; i < BSZ * NDIM / 4; i += gsz) {
        float4 v = reinterpret_cast<const float4*>(x)[i];
        uint2 hu, lu; split4(v, hu, lu);
        *reinterpret_cast<uint2*>(&g_xh[4 * i]) = hu;
        *reinterpret_cast<uint2*>(&g_xl[4 * i]) = lu;
    }
    for (int jb = bid; jb < 64; jb += gridDim.x) {
        if (jb < 32) fnorm_block(Wk1 + (size_t)jb * 8192, &g_F1p[jb], red);
        else         fnorm_block(Wk2 + (size_t)(jb - 32) * 8192, &g_F2p[jb - 32], red);
    }
    gbar();

    // ---------- Phase A: P1, 192 units (z3 x mh2 x n32) ----------
    for (int u = bid; u < 192; u += gridDim.x) {
        const int z = u / 64, r = u % 64, mh = r >> 5, n = r & 31;
        const float* W1 = (z == 0) ? Wf1 : (z == 1) ? Wg1 : Wk1;
        const float* b1 = (z == 0) ? bf1 : (z == 1) ? bg1 : bk1;
        p1_unit(smem, sb, z, mh, n, W1, b1);
        __syncthreads();
    }
    gbar();

    // ---------- Phase B: P2, 192 units (z3 x mh2 x n4 x s8) ----------
    for (int u = bid; u < 192; u += gridDim.x) {
        const int z = u / 64, r = u % 64, mh = r >> 5, rr = r & 31;
        const int n = rr >> 3, s = rr & 7;
        const float* W2 = (z == 0) ? Wf2 : (z == 1) ? Wg2 : Wk2;
        p2_unit(smem, sb, z, mh, n, s, W2);
        __syncthreads();
    }
    gbar();

    // ---------- Phase C: fgk, speculative out, per-row certification ----------
    if (bid < BSZ) {
        const int b = bid, i = tid;
        const int idx = b * NDIM + i;
        float fv = bf2[i], gv = bg2[i], kv = bk2[i];
#pragma unroll
        for (int s = 0; s < 8; s++) {
            fv += g_P2p[0][s][idx];
            gv += g_P2p[1][s][idx];
            kv += g_P2p[2][s][idx];
        }
        g_fgk[0][idx] = fv; g_fgk[1][idx] = gv; g_fgk[2][idx] = kv;
        out[idx] = 0.5f * (fv + gv);          // speculative (certified below)

        float kn2 = kv * kv, gn2 = gv * gv;
#pragma unroll
        for (int off = 16; off > 0; off >>= 1) {
            kn2 += __shfl_down_sync(0xffffffffu, kn2, off);
            gn2 += __shfl_down_sync(0xffffffffu, gn2, off);
        }
        const int warp = i >> 5, lane = i & 31;
        if (lane == 0) { red[warp] = kn2; red[8 + warp] = gn2; }
        __syncthreads();
        if (i == 0) {
            float tkn2 = 0.f, tgn2 = 0.f;
#pragma unroll
            for (int ww = 0; ww < 8; ww++) { tkn2 += red[ww]; tgn2 += red[8 + ww]; }
            float F1sq = 0.f, F2sq = 0.f;
#pragma unroll
            for (int p = 0; p < 32; p++) { F1sq += g_F1p[p]; F2sq += g_F2p[p]; }
            const float F  = sqrtf(F1sq) * sqrtf(F2sq);
            const float kn = sqrtf(tkn2), gn = sqrtf(tgn2);
            const float kn10 = tkn2 * tkn2 * tkn2 * tkn2 * tkn2;
            const int certified = (BETA * kn10 > 2.0f * kn * F * gn + 1.0f);
            g_bad[b] = certified ? 0 : 1;
        }
        __syncthreads();
    }
    gbar();

    // ---------- decision (uniform across grid) ----------
    {
        int bad = (tid < BSZ) ? g_bad[tid] : 0;
        if (__syncthreads_or(bad) == 0) return;   // fast path done
    }

    // ================= FALLBACK (certified-impossible, but exact) =================
    for (int i = gtid; i < BSZ * HDIM; i += gsz) {
        const float t = __bfloat162float(g_Hh[2][i]) + __bfloat162float(g_Hl[2][i]);
        g_D[i] = 1.0f - t * t;
    }
    for (int i = gtid; i < 2 * BSZ * NDIM; i += gsz) {
        const int z = i / (BSZ * NDIM), j = i - z * (BSZ * NDIM);
        __nv_bfloat16 h, l;
        split_bf16(g_fgk[z][j], h, l);
        g_fgh[z][j] = h; g_fgl[z][j] = l;
    }
    {
        float (*ts)[65] = reinterpret_cast<float(*)[65]>(smem);
        for (int t = bid; t < 128; t += gridDim.x) {
            if (t < 64)
                trans_tile(ts, Wk1, NDIM, (t >> 2) * 64, (t & 3) * 64, g_K1Th, g_K1Tl, HDIM);
            else {
                const int tt = t - 64;
                trans_tile(ts, Wk2, HDIM, (tt & 3) * 64, (tt >> 2) * 64, g_K2Th, g_K2Tl, NDIM);
            }
        }
    }
    gbar();
    gemm_phase(sb, 64, DecP3{});
    gbar();
    for (int i = gtid; i < 2 * BSZ * HDIM; i += gsz) {
        const int z = i / (BSZ * HDIM), j = i - z * (BSZ * HDIM);
        const float v = (g_P3p[z][0][j] + g_P3p[z][1][j]) * g_D[j];
        __nv_bfloat16 h, l;
        split_bf16(v, h, l);
        g_dvh[z][j] = h; g_dvl[z][j] = l;
    }
    gbar();
    gemm_phase(sb, 64, DecP4{});
    gbar();
    if (bid < BSZ) {
        const int b = bid, i = tid;
        const int idx = b * NDIM + i;
        float jfv = 0.f, jgv = 0.f;
#pragma unroll
        for (int s = 0; s < 8; s++) {
            jfv += g_P4p[0][s][idx];
            jgv += g_P4p[1][s][idx];
        }
        const float fv = g_fgk[0][idx];
        const float gv = g_fgk[1][idx];
        const float kv = g_fgk[2][idx];
        float kn2 = kv * kv, jf2 = jfv * jfv, dt = kv * jgv;
#pragma unroll
        for (int off = 16; off > 0; off >>= 1) {
            kn2 += __shfl_down_sync(0xffffffffu, kn2, off);
            jf2 += __shfl_down_sync(0xffffffffu, jf2, off);
            dt  += __shfl_down_sync(0xffffffffu, dt,  off);
        }
        const int warp = i >> 5, lane = i & 31;
        if (lane == 0) { red[warp] = kn2; red[8 + warp] = jf2; red[16 + warp] = dt; }
        __syncthreads();
        __shared__ float s_scale;
        if (i == 0) {
            float tkn2 = 0.f, tjf2 = 0.f, tdt = 0.f;
#pragma unroll
            for (int ww = 0; ww < 8; ww++) {
                tkn2 += red[ww]; tjf2 += red[8 + ww]; tdt += red[16 + ww];
            }
            const float kn   = sqrtf(tkn2);
            const float kn9  = tkn2 * tkn2 * tkn2 * tkn2 * kn;
            const float kn10 = kn9 * kn;
            const float c1 = sqrtf(tjf2) - ALPHA * kn9;
            const float c2 = tdt - BETA * kn10;
            s_scale = ((c1 > EPSC) || (c2 < -EPSC)) ? 0.5f : 1.0f;
        }
        __syncthreads();
        out[idx] = s_scale * (fv + gv);
    }
}

// inputs: 0:t 1:x 2:Wf1 3:bf1 4:Wf2 5:bf2 6:Wg1 7:bg1 8:Wg2 9:bg2 10:Wk1 11:bk1 12:Wk2 13:bk2
extern "C" void kernel_launch(void* const* d_in, const int* in_sizes, int n_in,
                              void* d_out, int out_size)
{
    const float* x   = (const float*)d_in[1];
    const float* Wf1 = (const float*)d_in[2];
    const float* bf1 = (const float*)d_in[3];
    const float* Wf2 = (const float*)d_in[4];
    const float* bf2 = (const float*)d_in[5];
    const float* Wg1 = (const float*)d_in[6];
    const float* bg1 = (const float*)d_in[7];
    const float* Wg2 = (const float*)d_in[8];
    const float* bg2 = (const float*)d_in[9];
    const float* Wk1 = (const float*)d_in[10];
    const float* bk1 = (const float*)d_in[11];
    const float* Wk2 = (const float*)d_in[12];
    const float* bk2 = (const float*)d_in[13];
    float* out = (float*)d_out;

    cudaFuncSetAttribute(fused_v3_kernel,
                         cudaFuncAttributeMaxDynamicSharedMemorySize, SMEM_TOTAL);

    int dev = 0, sms = 148;
    cudaGetDevice(&dev);
    cudaDeviceGetAttribute(&sms, cudaDevAttrMultiProcessorCount, dev);
    int occ = 1;
    cudaOccupancyMaxActiveBlocksPerMultiprocessor(&occ, fused_v3_kernel, 256, SMEM_TOTAL);
    if (occ < 1) occ = 1;
    if (occ > 2) occ = 2;
    const int grid = sms * occ;

    fused_v3_kernel<<<grid, 256, SMEM_TOTAL>>>(x, Wf1, bf1, Wf2, bf2, Wg1, bg1,
                                               Wg2, bg2, Wk1, bk1, Wk2, bk2, out);
}

// round 12
// speedup vs baseline: 1.0837x; 1.0837x over previous
#include <cuda_runtime.h>
#include <cuda_bf16.h>
#include <math.h>
#include <stdint.h>

#define BSZ  128
#define NDIM 256
#define HDIM 1024
#define ALPHA 60.0f
#define BETA  20.0f
#define EPSC  1e-8f

typedef unsigned int uint;

// ---------------- scratch (allocation-free __device__ globals) ----------------
__device__ __align__(16) __nv_bfloat16 g_xh[BSZ * NDIM],    g_xl[BSZ * NDIM];
__device__ __align__(16) __nv_bfloat16 g_Hh[3][BSZ * HDIM], g_Hl[3][BSZ * HDIM]; // only [2] written (fallback D)
__device__ __align__(16) float         g_fgk[3][BSZ * NDIM];
__device__ __align__(16) float         g_P2p[3][16][BSZ * NDIM];
__device__ float g_F1p[32], g_F2p[32];
__device__ int   g_bad[BSZ];

// fallback-only scratch
__device__ __align__(16) __nv_bfloat16 g_K2Th[HDIM * NDIM],  g_K2Tl[HDIM * NDIM];
__device__ __align__(16) __nv_bfloat16 g_K1Th[NDIM * HDIM],  g_K1Tl[NDIM * HDIM];
__device__ __align__(16) float         g_D[BSZ * HDIM];
__device__ __align__(16) __nv_bfloat16 g_fgh[2][BSZ * NDIM], g_fgl[2][BSZ * NDIM];
__device__ __align__(16) __nv_bfloat16 g_dvh[2][BSZ * HDIM], g_dvl[2][BSZ * HDIM];
__device__ __align__(16) float         g_P3p[2][2][BSZ * HDIM];
__device__ __align__(16) float         g_P4p[2][8][BSZ * NDIM];

// ---------------- grid barrier ----------------
__device__ int g_cnt = 0, g_sense = 0;
__device__ __forceinline__ void gbar()
{
    __threadfence();
    __syncthreads();
    if (threadIdx.x == 0) {
        int s = *(volatile int*)&g_sense;
        int old = atomicAdd(&g_cnt, 1);
        if (old == (int)gridDim.x - 1) {
            atomicExch(&g_cnt, 0);
            __threadfence();
            atomicExch(&g_sense, 1 - s);
        } else {
            while (*(volatile int*)&g_sense == s) __nanosleep(64);
        }
        __threadfence();
    }
    __syncthreads();
}

// ---------------- helpers ----------------
__device__ __forceinline__ uint smem_u32(const void* p)
{
    uint a;
    asm("{ .reg .u64 t; cvta.to.shared.u64 t, %1; cvt.u32.u64 %0, t; }"
        : "=r"(a) : "l"(p));
    return a;
}
__device__ __forceinline__ void split_bf16(float v, __nv_bfloat16& h, __nv_bfloat16& l)
{
    h = __float2bfloat16(v);
    l = __float2bfloat16(v - __bfloat162float(h));
}
__device__ __forceinline__ void st_bf2(__nv_bfloat16* p, __nv_bfloat16 a, __nv_bfloat16 b)
{
    __nv_bfloat162 t; t.x = a; t.y = b;
    *reinterpret_cast<__nv_bfloat162*>(p) = t;
}
__device__ __forceinline__ uint pack2(__nv_bfloat16 a, __nv_bfloat16 b)
{
    __nv_bfloat162 t; t.x = a; t.y = b;
    return *reinterpret_cast<uint*>(&t);
}
__device__ __forceinline__ void split4(float4 v, uint2& hu, uint2& lu)
{
    __nv_bfloat16 h0, l0, h1, l1, h2, l2, h3, l3;
    split_bf16(v.x, h0, l0); split_bf16(v.y, h1, l1);
    split_bf16(v.z, h2, l2); split_bf16(v.w, h3, l3);
    hu.x = pack2(h0, h1); hu.y = pack2(h2, h3);
    lu.x = pack2(l0, l1); lu.y = pack2(l2, l3);
}
__device__ __forceinline__ float frcp(float x)
{
    float r;
    asm("rcp.approx.f32 %0, %1;" : "=f"(r) : "f"(x));
    return r;
}
__device__ __forceinline__ float ftanh(float x)
{
    float ax = fabsf(x);
    float e = __expf(ax + ax);
    float t = 1.0f - 2.0f * frcp(e + 1.0f);
    return copysignf(t, x);
}

#define CP16(dst, src) \
    asm volatile("cp.async.cg.shared.global [%0], [%1], 16;" :: "r"(dst), "l"(src))
#define CP_COMMIT() asm volatile("cp.async.commit_group;" ::: "memory")
#define CP_WAIT(n)  asm volatile("cp.async.wait_group %0;" :: "n"(n) : "memory")

#define LDM4(r, addr) \
    asm volatile("ldmatrix.sync.aligned.m8n8.x4.shared.b16 {%0,%1,%2,%3}, [%4];" \
        : "=r"((r)[0]), "=r"((r)[1]), "=r"((r)[2]), "=r"((r)[3]) : "r"(addr))

#define MMA16816(c, a, b0, b1) \
    asm volatile("mma.sync.aligned.m16n8k16.row.col.f32.bf16.bf16.f32 " \
        "{%0,%1,%2,%3}, {%4,%5,%6,%7}, {%8,%9}, {%0,%1,%2,%3};" \
        : "+f"((c)[0]), "+f"((c)[1]), "+f"((c)[2]), "+f"((c)[3]) \
        : "r"((a)[0]), "r"((a)[1]), "r"((a)[2]), "r"((a)[3]), "r"(b0), "r"(b1))

// ---------------- smem layouts ----------------
// fast path:
//   Hc A-buffer:  [0, 8K) h, [8K, 16K) l            (64 rows x K64)
//   stage-1 double bufs at 16K + b*32K:
//        x Ah [0,8K) Al [8K,16K)  W1 Bh [16K,24K) Bl [24K,32K)
//   stage-2 B reuses [16K, 48K): Bh [16K,32K) Bl [32K,48K)  (128 rows x K64)
// fallback buffers (verified):
#define BUF_AL 16384
#define BUF_BH 32768
#define BUF_BL 40960
#define BUF_SZ 49152
#define SMEM_TOTAL (2 * BUF_SZ)

// ============================================================
// compute_m64<NJG>: 64 x (NJG*32) tile, one K=64 chunk.
// 8 warps: 4m x 2n; warp tile 16 x (NJG*16). acc[NJG*2][4].
// ============================================================
template <int NJG>
__device__ __forceinline__ void compute_m64(uint buf, uint al_off, uint bh_off,
                                            uint bl_off, float acc[][4])
{
    const int lane = threadIdx.x & 31;
    const int w = threadIdx.x >> 5;
    const int m0w = (w & 3) * 16;
    const int n0w = (w >> 2) * (NJG * 16);
    const int arow = m0w + (lane & 15);
    const int au_l = lane >> 4;
    const int brow_l = (lane & 7) + ((lane >> 4) & 1) * 8;
    const int bu_l = (lane >> 3) & 1;

#pragma unroll
    for (int ks = 0; ks < 4; ks++) {
        uint ah[4], al[4], bh[NJG][4], bl[NJG][4];
        {
            const int u = ks * 2 + au_l;
            const uint ad = buf + (uint)arow * 128 + (uint)((u ^ (arow & 7)) * 16);
            LDM4(ah, ad);
            LDM4(al, ad + al_off);
        }
#pragma unroll
        for (int njp = 0; njp < NJG; njp++) {
            const int r = n0w + njp * 16 + brow_l;
            const int u = ks * 2 + bu_l;
            const uint bd = buf + bh_off + (uint)r * 128 + (uint)((u ^ (r & 7)) * 16);
            LDM4(bh[njp], bd);
            LDM4(bl[njp], bd + (bl_off - bh_off));
        }
#pragma unroll
        for (int njp = 0; njp < NJG; njp++)
#pragma unroll
            for (int h = 0; h < 2; h++) {
                float* c = acc[njp * 2 + h];
                MMA16816(c, ah, bh[njp][2 * h], bh[njp][2 * h + 1]);
                MMA16816(c, ah, bl[njp][2 * h], bl[njp][2 * h + 1]);
                MMA16816(c, al, bh[njp][2 * h], bh[njp][2 * h + 1]);
            }
    }
}

// ============================================================
// Fused unit (z, s, mh, nh):
//  Stage 1: Hc[64,64] = tanh(x[mh*64..][:,:] @ W1[z][s*64..+64,:]^T + b1)
//           kept in SMEM (A-tile layout, h/l); z==2&&nh==0 also stores to g_Hh/Hl[2]
//  Stage 2: g_P2p[z][s][mh rows, nh*128 cols] = Hc @ W2[z][nh*128..+128, s*64..+64]^T
// ============================================================
__device__ void fused_unit(char* smem, uint sb, int z, int s, int mh, int nh,
                           const float* __restrict__ W1,
                           const float* __restrict__ b1,
                           const float* __restrict__ W2)
{
    const int tid = threadIdx.x;
    const int lane = tid & 31, w = tid >> 5;
    const __nv_bfloat16* Axh = g_xh + (size_t)mh * 64 * NDIM;
    const __nv_bfloat16* Axl = g_xl + (size_t)mh * 64 * NDIM;
    const float* W1s = W1 + (size_t)s * 64 * NDIM;
    const uint sbuf[2] = {sb + 16384, sb + 49152};
    char* cb[2] = {smem + 16384, smem + 49152};

    float4 bw[4];
    auto ldgB1 = [&](int kc) {
#pragma unroll
        for (int i = 0; i < 4; i++) {
            const int idx = i * 256 + tid;
            bw[i] = *reinterpret_cast<const float4*>(
                &W1s[(size_t)(idx >> 4) * NDIM + kc + (idx & 15) * 4]);
        }
    };
    auto stsB1 = [&](char* b) {
#pragma unroll
        for (int i = 0; i < 4; i++) {
            const int idx = i * 256 + tid;
            const int row = idx >> 4;
            const int u2 = (idx & 15) >> 1, h8 = (idx & 1) * 8;
            const uint off = (uint)row * 128 + (uint)((u2 ^ (row & 7)) * 16) + h8;
            uint2 hu, lu; split4(bw[i], hu, lu);
            *reinterpret_cast<uint2*>(b + 16384 + off) = hu;
            *reinterpret_cast<uint2*>(b + 24576 + off) = lu;
        }
    };
    auto cpA = [&](uint b, int kc) {
#pragma unroll
        for (int i = 0; i < 2; i++) {
            const int idx = i * 256 + tid;
            const int row = idx >> 3, u2 = idx & 7;
            const uint off = (uint)row * 128 + (uint)((u2 ^ (row & 7)) * 16);
            CP16(b + off,        Axh + (size_t)row * NDIM + kc + u2 * 8);
            CP16(b + 8192 + off, Axl + (size_t)row * NDIM + kc + u2 * 8);
        }
        CP_COMMIT();
    };

    // ---- stage 1: K=256, 4 chunks, double-buffered ----
    float acc1[4][4];
#pragma unroll
    for (int a = 0; a < 4; a++)
#pragma unroll
        for (int q = 0; q < 4; q++) acc1[a][q] = 0.f;

    ldgB1(0);
    cpA(sbuf[0], 0);
    cpA(sbuf[1], 64);
    stsB1(cb[0]);
    ldgB1(64);
    CP_WAIT(1);
    __syncthreads();
#pragma unroll
    for (int c = 0; c < 4; c++) {
        compute_m64<2>(sbuf[c & 1], 8192, 16384, 24576, acc1);
        __syncthreads();
        if (c < 3) {
            stsB1(cb[(c + 1) & 1]);
            if (c < 2) {
                cpA(sbuf[c & 1], (c + 2) * 64);
                ldgB1((c + 2) * 64);
                CP_WAIT(1);
            } else {
                CP_WAIT(0);
            }
            __syncthreads();
        }
    }

    // ---- stage-1 epilogue: tanh + h/l split into Hc SMEM (fill_chunk layout) ----
    const int g = lane >> 2, t4 = lane & 3;
    const int m0w = (w & 3) * 16, n0w1 = (w >> 2) * 32;
    const bool storeH = (z == 2 && nh == 0);
#pragma unroll
    for (int j = 0; j < 4; j++) {
        const int njp = j >> 1, h = j & 1;
        const int kk = n0w1 + njp * 16 + h * 8 + t4 * 2;    // 0..63, even
        const float bv0 = b1[s * 64 + kk];
        const float bv1 = b1[s * 64 + kk + 1];
        const uint ubase = (uint)((kk >> 3));
#pragma unroll
        for (int half = 0; half < 2; half++) {
            const int r = m0w + g + half * 8;
            const float h0 = ftanh(acc1[j][half * 2 + 0] + bv0);
            const float h1 = ftanh(acc1[j][half * 2 + 1] + bv1);
            __nv_bfloat16 p0, q0, p1, q1;
            split_bf16(h0, p0, q0); split_bf16(h1, p1, q1);
            const uint off = (uint)r * 128 + ((ubase ^ (uint)(r & 7)) * 16) + (uint)(t4 * 4);
            *reinterpret_cast<uint*>(smem + off)        = pack2(p0, p1);
            *reinterpret_cast<uint*>(smem + 8192 + off) = pack2(q0, q1);
            if (storeH) {
                const size_t go = (size_t)(mh * 64 + r) * HDIM + s * 64 + kk;
                st_bf2(&g_Hh[2][go], p0, p1);
                st_bf2(&g_Hl[2][go], q0, q1);
            }
        }
    }
    __syncthreads();

    // ---- stage 2: B = W2 slice (128 rows x K64), single chunk ----
    const float* W2s = W2 + (size_t)nh * 128 * HDIM;
#pragma unroll
    for (int p = 0; p < 2; p++) {
        float4 bb[4];
#pragma unroll
        for (int i = 0; i < 4; i++) {
            const int idx = (p * 4 + i) * 256 + tid;
            bb[i] = *reinterpret_cast<const float4*>(
                &W2s[(size_t)(idx >> 4) * HDIM + s * 64 + (idx & 15) * 4]);
        }
#pragma unroll
        for (int i = 0; i < 4; i++) {
            const int idx = (p * 4 + i) * 256 + tid;
            const int row = idx >> 4;
            const int u2 = (idx & 15) >> 1, h8 = (idx & 1) * 8;
            const uint off = (uint)row * 128 + (uint)((u2 ^ (row & 7)) * 16) + h8;
            uint2 hu, lu; split4(bb[i], hu, lu);
            *reinterpret_cast<uint2*>(smem + 16384 + off) = hu;
            *reinterpret_cast<uint2*>(smem + 32768 + off) = lu;
        }
    }
    __syncthreads();

    float acc2[8][4];
#pragma unroll
    for (int a = 0; a < 8; a++)
#pragma unroll
        for (int q = 0; q < 4; q++) acc2[a][q] = 0.f;
    compute_m64<4>(sb, 8192, 16384, 32768, acc2);

    // ---- stage-2 epilogue: fp32 partial ----
    float* O = g_P2p[z][s];
    const int n0w2 = (w >> 2) * 64;
#pragma unroll
    for (int j = 0; j < 8; j++) {
        const int njp = j >> 1, h = j & 1;
        const int col = nh * 128 + n0w2 + njp * 16 + h * 8 + t4 * 2;
        const int row = mh * 64 + m0w + g;
        *reinterpret_cast<float2*>(&O[(size_t)row * NDIM + col]) =
            make_float2(acc2[j][0], acc2[j][1]);
        *reinterpret_cast<float2*>(&O[(size_t)(row + 8) * NDIM + col]) =
            make_float2(acc2[j][2], acc2[j][3]);
    }
}

// ================= fallback machinery (verified; certified-unused) =============
__device__ __forceinline__ void compute64(uint buf, float acc[2][4][4])
{
    const int lane = threadIdx.x & 31;
    const int w = threadIdx.x >> 5;
    const int m0w = (w & 3) * 32;
    const int n0w = (w >> 2) * 32;
    const int arow_l = lane & 15;
    const int au_l   = lane >> 4;
    const int brow_l = (lane & 7) + ((lane >> 4) & 1) * 8;
    const int bu_l   = (lane >> 3) & 1;
#pragma unroll
    for (int ks = 0; ks < 4; ks++) {
        uint ah[2][4], al[2][4], bh[2][4], bl[2][4];
#pragma unroll
        for (int mi = 0; mi < 2; mi++) {
            const int r = m0w + mi * 16 + arow_l;
            const int u = ks * 2 + au_l;
            const uint ad = buf + (uint)r * 128 + (uint)((u ^ (r & 7)) * 16);
            LDM4(ah[mi], ad);
            LDM4(al[mi], ad + BUF_AL);
        }
#pragma unroll
        for (int njp = 0; njp < 2; njp++) {
            const int r = n0w + njp * 16 + brow_l;
            const int u = ks * 2 + bu_l;
            const uint bd = buf + BUF_BH + (uint)r * 128 + (uint)((u ^ (r & 7)) * 16);
            LDM4(bh[njp], bd);
            LDM4(bl[njp], bd + (BUF_BL - BUF_BH));
        }
#pragma unroll
        for (int mi = 0; mi < 2; mi++)
#pragma unroll
            for (int njp = 0; njp < 2; njp++)
#pragma unroll
                for (int h = 0; h < 2; h++) {
                    float* c = acc[mi][njp * 2 + h];
                    MMA16816(c, ah[mi], bh[njp][2 * h], bh[njp][2 * h + 1]);
                    MMA16816(c, ah[mi], bl[njp][2 * h], bl[njp][2 * h + 1]);
                    MMA16816(c, al[mi], bh[njp][2 * h], bh[njp][2 * h + 1]);
                }
    }
}
struct Job {
    const __nv_bfloat16 *Ah, *Al, *Bh, *Bl;
    int lda, ldb, k0, nch, ldo;
    float* Of;
};
__device__ __forceinline__ void fill_chunk(uint buf, const Job& j, int kc)
{
    const int tid = threadIdx.x;
#pragma unroll
    for (int i = 0; i < 4; i++) {
        const int idx = tid + i * 256;
        const int row = idx >> 3, u = idx & 7;
        const uint sw = (uint)row * 128 + (uint)((u ^ (row & 7)) * 16);
        const size_t go = (size_t)row * j.lda + kc + u * 8;
        CP16(buf + sw,          j.Ah + go);
        CP16(buf + BUF_AL + sw, j.Al + go);
    }
#pragma unroll
    for (int i = 0; i < 2; i++) {
        const int idx = tid + i * 256;
        const int row = idx >> 3, u = idx & 7;
        const uint sw = (uint)row * 128 + (uint)((u ^ (row & 7)) * 16);
        const size_t go = (size_t)row * j.ldb + kc + u * 8;
        CP16(buf + BUF_BH + sw, j.Bh + go);
        CP16(buf + BUF_BL + sw, j.Bl + go);
    }
    CP_COMMIT();
}
__device__ __forceinline__ void store_tile(const Job& j, const float acc[2][4][4])
{
    const int lane = threadIdx.x & 31;
    const int w = threadIdx.x >> 5;
    const int g = lane >> 2, t = lane & 3;
    const int m0w = (w & 3) * 32, n0w = (w >> 2) * 32;
#pragma unroll
    for (int mi = 0; mi < 2; mi++)
#pragma unroll
        for (int nj = 0; nj < 4; nj++) {
            const int r = m0w + mi * 16 + g, c = n0w + nj * 8 + t * 2;
            *reinterpret_cast<float2*>(&j.Of[(size_t)r * j.ldo + c]) =
                make_float2(acc[mi][nj][0], acc[mi][nj][1]);
            *reinterpret_cast<float2*>(&j.Of[(size_t)(r + 8) * j.ldo + c]) =
                make_float2(acc[mi][nj][2], acc[mi][nj][3]);
        }
}
template <class DEC>
__device__ void gemm_phase(uint sb, int U, const DEC& dec)
{
    const uint buf0 = sb, buf1 = sb + BUF_SZ;
    for (int u = blockIdx.x; u < U; u += gridDim.x) {
        Job j; dec(u, j);
        fill_chunk(buf0, j, j.k0);
        fill_chunk(buf1, j, j.k0 + 64);
        float acc[2][4][4];
#pragma unroll
        for (int a = 0; a < 2; a++)
#pragma unroll
            for (int b = 0; b < 4; b++)
#pragma unroll
                for (int q = 0; q < 4; q++) acc[a][b][q] = 0.f;
        for (int c = 0; c < j.nch; c++) {
            if (c == j.nch - 1) { CP_WAIT(0); } else { CP_WAIT(1); }
            __syncthreads();
            compute64((c & 1) ? buf1 : buf0, acc);
            __syncthreads();
            if (c + 2 < j.nch)
                fill_chunk((c & 1) ? buf1 : buf0, j, j.k0 + (c + 2) * 64);
        }
        store_tile(j, acc);
        __syncthreads();
    }
}
struct DecP3 {
    __device__ void operator()(int u, Job& j) const {
        const int z = u >> 5, r = u & 31, n = r >> 1, s = r & 1;
        j.Ah = g_fgh[z]; j.Al = g_fgl[z]; j.lda = NDIM;
        j.Bh = g_K2Th + (size_t)n * 64 * NDIM;
        j.Bl = g_K2Tl + (size_t)n * 64 * NDIM; j.ldb = NDIM;
        j.k0 = s * 128; j.nch = 2;
        j.Of = g_P3p[z][s] + n * 64; j.ldo = HDIM;
    }
};
struct DecP4 {
    __device__ void operator()(int u, Job& j) const {
        const int z = u >> 5, r = u & 31, n = r >> 3, s = r & 7;
        j.Ah = g_dvh[z]; j.Al = g_dvl[z]; j.lda = HDIM;
        j.Bh = g_K1Th + (size_t)n * 64 * HDIM;
        j.Bl = g_K1Tl + (size_t)n * 64 * HDIM; j.ldb = HDIM;
        j.k0 = s * 128; j.nch = 2;
        j.Of = g_P4p[z][s] + n * 64; j.ldo = NDIM;
    }
};
__device__ void fnorm_block(const float* __restrict__ W, float* slot, float* red)
{
    float s = 0.f;
    for (int i = threadIdx.x; i < 2048; i += 256) {
        float4 v = reinterpret_cast<const float4*>(W)[i];
        s += v.x * v.x + v.y * v.y + v.z * v.z + v.w * v.w;
    }
#pragma unroll
    for (int off = 16; off > 0; off >>= 1) s += __shfl_down_sync(0xffffffffu, s, off);
    const int warp = threadIdx.x >> 5, lane = threadIdx.x & 31;
    if (lane == 0) red[warp] = s;
    __syncthreads();
    if (threadIdx.x == 0) {
        float t = 0.f;
#pragma unroll
        for (int ww = 0; ww < 8; ww++) t += red[ww];
        *slot = t;
    }
    __syncthreads();
}
__device__ void trans_tile(float (*ts)[65], const float* __restrict__ src, int lds,
                           int r0, int c0, __nv_bfloat16* dh, __nv_bfloat16* dl, int ldd)
{
    const int tid = threadIdx.x;
    __syncthreads();
    for (int i = tid; i < 4096; i += 256) {
        const int r = i >> 6, c = i & 63;
        ts[r][c] = src[(size_t)(r0 + r) * lds + c0 + c];
    }
    __syncthreads();
    for (int i = tid; i < 4096; i += 256) {
        const int dr = i >> 6, dc = i & 63;
        __nv_bfloat16 h, l;
        split_bf16(ts[dc][dr], h, l);
        dh[(size_t)(c0 + dr) * ldd + r0 + dc] = h;
        dl[(size_t)(c0 + dr) * ldd + r0 + dc] = l;
    }
}

// ---------------- persistent fused kernel ----------------
__global__ __launch_bounds__(256, 2) void fused_v4_kernel(
    const float* __restrict__ x,
    const float* __restrict__ Wf1, const float* __restrict__ bf1,
    const float* __restrict__ Wf2, const float* __restrict__ bf2,
    const float* __restrict__ Wg1, const float* __restrict__ bg1,
    const float* __restrict__ Wg2, const float* __restrict__ bg2,
    const float* __restrict__ Wk1, const float* __restrict__ bk1,
    const float* __restrict__ Wk2, const float* __restrict__ bk2,
    float* __restrict__ out)
{
    extern __shared__ char smem[];
    const uint sb = smem_u32(smem);
    float* red = reinterpret_cast<float*>(smem);
    const int tid = threadIdx.x;
    const int bid = blockIdx.x;
    const int gtid = bid * 256 + tid;
    const int gsz = gridDim.x * 256;

    // ---------- PhPre: convert x + Frobenius norms ----------
    for (int i = gtid; i < BSZ * NDIM / 4; i += gsz) {
        float4 v = reinterpret_cast<const float4*>(x)[i];
        uint2 hu, lu; split4(v, hu, lu);
        *reinterpret_cast<uint2*>(&g_xh[4 * i]) = hu;
        *reinterpret_cast<uint2*>(&g_xl[4 * i]) = lu;
    }
    for (int jb = bid; jb < 64; jb += gridDim.x) {
        if (jb < 32) fnorm_block(Wk1 + (size_t)jb * 8192, &g_F1p[jb], red);
        else         fnorm_block(Wk2 + (size_t)(jb - 32) * 8192, &g_F2p[jb - 32], red);
    }
    gbar();

    // ---------- Phase AB: 192 fused units (z3 x s16 x mh2 x nh2) ----------
    for (int u = bid; u < 192; u += gridDim.x) {
        const int z = u / 64, r = u % 64;
        const int s = r & 15, mh = (r >> 4) & 1, nh = (r >> 5) & 1;
        const float* W1 = (z == 0) ? Wf1 : (z == 1) ? Wg1 : Wk1;
        const float* b1 = (z == 0) ? bf1 : (z == 1) ? bg1 : bk1;
        const float* W2 = (z == 0) ? Wf2 : (z == 1) ? Wg2 : Wk2;
        fused_unit(smem, sb, z, s, mh, nh, W1, b1, W2);
        __syncthreads();
    }
    gbar();

    // ---------- Phase C: fgk, speculative out, per-row certification ----------
    if (bid < BSZ) {
        const int b = bid, i = tid;
        const int idx = b * NDIM + i;
        float fv = bf2[i], gv = bg2[i], kv = bk2[i];
#pragma unroll
        for (int s = 0; s < 16; s++) {
            fv += g_P2p[0][s][idx];
            gv += g_P2p[1][s][idx];
            kv += g_P2p[2][s][idx];
        }
        g_fgk[0][idx] = fv; g_fgk[1][idx] = gv; g_fgk[2][idx] = kv;
        out[idx] = 0.5f * (fv + gv);          // speculative (certified below)

        float kn2 = kv * kv, gn2 = gv * gv;
#pragma unroll
        for (int off = 16; off > 0; off >>= 1) {
            kn2 += __shfl_down_sync(0xffffffffu, kn2, off);
            gn2 += __shfl_down_sync(0xffffffffu, gn2, off);
        }
        const int warp = i >> 5, lane = i & 31;
        if (lane == 0) { red[warp] = kn2; red[8 + warp] = gn2; }
        __syncthreads();
        if (i == 0) {
            float tkn2 = 0.f, tgn2 = 0.f;
#pragma unroll
            for (int ww = 0; ww < 8; ww++) { tkn2 += red[ww]; tgn2 += red[8 + ww]; }
            float F1sq = 0.f, F2sq = 0.f;
#pragma unroll
            for (int p = 0; p < 32; p++) { F1sq += g_F1p[p]; F2sq += g_F2p[p]; }
            const float F  = sqrtf(F1sq) * sqrtf(F2sq);
            const float kn = sqrtf(tkn2), gn = sqrtf(tgn2);
            const float kn10 = tkn2 * tkn2 * tkn2 * tkn2 * tkn2;
            const int certified = (BETA * kn10 > 2.0f * kn * F * gn + 1.0f);
            g_bad[b] = certified ? 0 : 1;
        }
        __syncthreads();
    }
    gbar();

    // ---------- decision (uniform across grid) ----------
    {
        int bad = (tid < BSZ) ? g_bad[tid] : 0;
        if (__syncthreads_or(bad) == 0) return;   // fast path done
    }

    // ================= FALLBACK (certified-impossible, but exact) =================
    for (int i = gtid; i < BSZ * HDIM; i += gsz) {
        const float t = __bfloat162float(g_Hh[2][i]) + __bfloat162float(g_Hl[2][i]);
        g_D[i] = 1.0f - t * t;
    }
    for (int i = gtid; i < 2 * BSZ * NDIM; i += gsz) {
        const int z = i / (BSZ * NDIM), j = i - z * (BSZ * NDIM);
        __nv_bfloat16 h, l;
        split_bf16(g_fgk[z][j], h, l);
        g_fgh[z][j] = h; g_fgl[z][j] = l;
    }
    {
        float (*ts)[65] = reinterpret_cast<float(*)[65]>(smem);
        for (int t = bid; t < 128; t += gridDim.x) {
            if (t < 64)
                trans_tile(ts, Wk1, NDIM, (t >> 2) * 64, (t & 3) * 64, g_K1Th, g_K1Tl, HDIM);
            else {
                const int tt = t - 64;
                trans_tile(ts, Wk2, HDIM, (tt & 3) * 64, (tt >> 2) * 64, g_K2Th, g_K2Tl, NDIM);
            }
        }
    }
    gbar();
    gemm_phase(sb, 64, DecP3{});
    gbar();
    for (int i = gtid; i < 2 * BSZ * HDIM; i += gsz) {
        const int z = i / (BSZ * HDIM), j = i - z * (BSZ * HDIM);
        const float v = (g_P3p[z][0][j] + g_P3p[z][1][j]) * g_D[j];
        __nv_bfloat16 h, l;
        split_bf16(v, h, l);
        g_dvh[z][j] = h; g_dvl[z][j] = l;
    }
    gbar();
    gemm_phase(sb, 64, DecP4{});
    gbar();
    if (bid < BSZ) {
        const int b = bid, i = tid;
        const int idx = b * NDIM + i;
        float jfv = 0.f, jgv = 0.f;
#pragma unroll
        for (int s = 0; s < 8; s++) {
            jfv += g_P4p[0][s][idx];
            jgv += g_P4p[1][s][idx];
        }
        const float fv = g_fgk[0][idx];
        const float gv = g_fgk[1][idx];
        const float kv = g_fgk[2][idx];
        float kn2 = kv * kv, jf2 = jfv * jfv, dt = kv * jgv;
#pragma unroll
        for (int off = 16; off > 0; off >>= 1) {
            kn2 += __shfl_down_sync(0xffffffffu, kn2, off);
            jf2 += __shfl_down_sync(0xffffffffu, jf2, off);
            dt  += __shfl_down_sync(0xffffffffu, dt,  off);
        }
        const int warp = i >> 5, lane = i & 31;
        if (lane == 0) { red[warp] = kn2; red[8 + warp] = jf2; red[16 + warp] = dt; }
        __syncthreads();
        __shared__ float s_scale;
        if (i == 0) {
            float tkn2 = 0.f, tjf2 = 0.f, tdt = 0.f;
#pragma unroll
            for (int ww = 0; ww < 8; ww++) {
                tkn2 += red[ww]; tjf2 += red[8 + ww]; tdt += red[16 + ww];
            }
            const float kn   = sqrtf(tkn2);
            const float kn9  = tkn2 * tkn2 * tkn2 * tkn2 * kn;
            const float kn10 = kn9 * kn;
            const float c1 = sqrtf(tjf2) - ALPHA * kn9;
            const float c2 = tdt - BETA * kn10;
            s_scale = ((c1 > EPSC) || (c2 < -EPSC)) ? 0.5f : 1.0f;
        }
        __syncthreads();
        out[idx] = s_scale * (fv + gv);
    }
}

// inputs: 0:t 1:x 2:Wf1 3:bf1 4:Wf2 5:bf2 6:Wg1 7:bg1 8:Wg2 9:bg2 10:Wk1 11:bk1 12:Wk2 13:bk2
extern "C" void kernel_launch(void* const* d_in, const int* in_sizes, int n_in,
                              void* d_out, int out_size)
{
    const float* x   = (const float*)d_in[1];
    const float* Wf1 = (const float*)d_in[2];
    const float* bf1 = (const float*)d_in[3];
    const float* Wf2 = (const float*)d_in[4];
    const float* bf2 = (const float*)d_in[5];
    const float* Wg1 = (const float*)d_in[6];
    const float* bg1 = (const float*)d_in[7];
    const float* Wg2 = (const float*)d_in[8];
    const float* bg2 = (const float*)d_in[9];
    const float* Wk1 = (const float*)d_in[10];
    const float* bk1 = (const float*)d_in[11];
    const float* Wk2 = (const float*)d_in[12];
    const float* bk2 = (const float*)d_in[13];
    float* out = (float*)d_out;

    cudaFuncSetAttribute(fused_v4_kernel,
                         cudaFuncAttributeMaxDynamicSharedMemorySize, SMEM_TOTAL);

    int dev = 0, sms = 148;
    cudaGetDevice(&dev);
    cudaDeviceGetAttribute(&sms, cudaDevAttrMultiProcessorCount, dev);
    int occ = 1;
    cudaOccupancyMaxActiveBlocksPerMultiprocessor(&occ, fused_v4_kernel, 256, SMEM_TOTAL);
    if (occ < 1) occ = 1;
    if (occ > 2) occ = 2;
    const int grid = sms * occ;

    fused_v4_kernel<<<grid, 256, SMEM_TOTAL>>>(x, Wf1, bf1, Wf2, bf2, Wg1, bg1,
                                               Wg2, bg2, Wk1, bk1, Wk2, bk2, out);
}

// round 13
// speedup vs baseline: 1.2782x; 1.1794x over previous
#include <cuda_runtime.h>
#include <cuda_bf16.h>
#include <math.h>
#include <stdint.h>

#define BSZ  128
#define NDIM 256
#define HDIM 1024
#define ALPHA 60.0f
#define BETA  20.0f
#define EPSC  1e-8f

typedef unsigned int uint;

// ---------------- scratch (allocation-free __device__ globals) ----------------
__device__ __align__(16) __nv_bfloat16 g_Hh[3][BSZ * HDIM], g_Hl[3][BSZ * HDIM];
__device__ __align__(16) float         g_fgk[3][BSZ * NDIM];
__device__ __align__(16) float         g_P2p[3][8][BSZ * NDIM];
__device__ float g_F1p[32], g_F2p[32];
__device__ int   g_bad[BSZ];
__device__ int   g_rdy[24];          // ready counters: [z*8+s], target 4

// fallback-only scratch
__device__ __align__(16) __nv_bfloat16 g_K2Th[HDIM * NDIM],  g_K2Tl[HDIM * NDIM];
__device__ __align__(16) __nv_bfloat16 g_K1Th[NDIM * HDIM],  g_K1Tl[NDIM * HDIM];
__device__ __align__(16) float         g_D[BSZ * HDIM];
__device__ __align__(16) __nv_bfloat16 g_fgh[2][BSZ * NDIM], g_fgl[2][BSZ * NDIM];
__device__ __align__(16) __nv_bfloat16 g_dvh[2][BSZ * HDIM], g_dvl[2][BSZ * HDIM];
__device__ __align__(16) float         g_P3p[2][2][BSZ * HDIM];
__device__ __align__(16) float         g_P4p[2][8][BSZ * NDIM];

// ---------------- grid barrier ----------------
__device__ int g_cnt = 0, g_sense = 0;
__device__ __forceinline__ void gbar()
{
    __threadfence();
    __syncthreads();
    if (threadIdx.x == 0) {
        int s = *(volatile int*)&g_sense;
        int old = atomicAdd(&g_cnt, 1);
        if (old == (int)gridDim.x - 1) {
            atomicExch(&g_cnt, 0);
            __threadfence();
            atomicExch(&g_sense, 1 - s);
        } else {
            while (*(volatile int*)&g_sense == s) __nanosleep(64);
        }
        __threadfence();
    }
    __syncthreads();
}

// ---------------- helpers ----------------
__device__ __forceinline__ uint smem_u32(const void* p)
{
    uint a;
    asm("{ .reg .u64 t; cvta.to.shared.u64 t, %1; cvt.u32.u64 %0, t; }"
        : "=r"(a) : "l"(p));
    return a;
}
__device__ __forceinline__ void split_bf16(float v, __nv_bfloat16& h, __nv_bfloat16& l)
{
    h = __float2bfloat16(v);
    l = __float2bfloat16(v - __bfloat162float(h));
}
__device__ __forceinline__ void st_bf2(__nv_bfloat16* p, __nv_bfloat16 a, __nv_bfloat16 b)
{
    __nv_bfloat162 t; t.x = a; t.y = b;
    *reinterpret_cast<__nv_bfloat162*>(p) = t;
}
__device__ __forceinline__ uint pack2(__nv_bfloat16 a, __nv_bfloat16 b)
{
    __nv_bfloat162 t; t.x = a; t.y = b;
    return *reinterpret_cast<uint*>(&t);
}
__device__ __forceinline__ void split4(float4 v, uint2& hu, uint2& lu)
{
    __nv_bfloat16 h0, l0, h1, l1, h2, l2, h3, l3;
    split_bf16(v.x, h0, l0); split_bf16(v.y, h1, l1);
    split_bf16(v.z, h2, l2); split_bf16(v.w, h3, l3);
    hu.x = pack2(h0, h1); hu.y = pack2(h2, h3);
    lu.x = pack2(l0, l1); lu.y = pack2(l2, l3);
}
__device__ __forceinline__ float frcp(float x)
{
    float r;
    asm("rcp.approx.f32 %0, %1;" : "=f"(r) : "f"(x));
    return r;
}
__device__ __forceinline__ float ftanh(float x)
{
    float ax = fabsf(x);
    float e = __expf(ax + ax);
    float t = 1.0f - 2.0f * frcp(e + 1.0f);
    return copysignf(t, x);
}

#define CP16(dst, src) \
    asm volatile("cp.async.cg.shared.global [%0], [%1], 16;" :: "r"(dst), "l"(src))
#define CP_COMMIT() asm volatile("cp.async.commit_group;" ::: "memory")
#define CP_WAIT(n)  asm volatile("cp.async.wait_group %0;" :: "n"(n) : "memory")

#define LDM4(r, addr) \
    asm volatile("ldmatrix.sync.aligned.m8n8.x4.shared.b16 {%0,%1,%2,%3}, [%4];" \
        : "=r"((r)[0]), "=r"((r)[1]), "=r"((r)[2]), "=r"((r)[3]) : "r"(addr))

#define MMA16816(c, a, b0, b1) \
    asm volatile("mma.sync.aligned.m16n8k16.row.col.f32.bf16.bf16.f32 " \
        "{%0,%1,%2,%3}, {%4,%5,%6,%7}, {%8,%9}, {%0,%1,%2,%3};" \
        : "+f"((c)[0]), "+f"((c)[1]), "+f"((c)[2]), "+f"((c)[3]) \
        : "r"((a)[0]), "r"((a)[1]), "r"((a)[2]), "r"((a)[3]), "r"(b0), "r"(b1))

// ---------------- smem layouts ----------------
#define BUF_AL 16384
#define BUF_BH 32768
#define BUF_BL 40960
#define BUF_SZ 49152
#define SMEM_TOTAL (2 * BUF_SZ)
// P1 sublayout within each 48K buffer: Ah 16K | Al 16K | Bh 4K | Bl 4K
#define P1_AL 16384
#define P1_BH 32768
#define P1_BL 36864

// ============================================================
// compute32: 128x32 tile, one K=64 chunk. 8 warps = 8m x 1n. (v2-verified)
// ============================================================
__device__ __forceinline__ void compute32(uint buf, float acc[4][4])
{
    const int lane = threadIdx.x & 31;
    const int w = threadIdx.x >> 5;
    const int arow = w * 16 + (lane & 15);
    const int au_l = lane >> 4;
    const int brow_l = (lane & 7) + ((lane >> 4) & 1) * 8;
    const int bu_l   = (lane >> 3) & 1;

#pragma unroll
    for (int ks = 0; ks < 4; ks++) {
        uint ah[4], al[4], bh[2][4], bl[2][4];
        {
            const int u = ks * 2 + au_l;
            const uint ad = buf + (uint)arow * 128 + (uint)((u ^ (arow & 7)) * 16);
            LDM4(ah, ad);
            LDM4(al, ad + P1_AL);
        }
#pragma unroll
        for (int njp = 0; njp < 2; njp++) {
            const int r = njp * 16 + brow_l;
            const int u = ks * 2 + bu_l;
            const uint bd = buf + P1_BH + (uint)r * 128 + (uint)((u ^ (r & 7)) * 16);
            LDM4(bh[njp], bd);
            LDM4(bl[njp], bd + (P1_BL - P1_BH));
        }
#pragma unroll
        for (int njp = 0; njp < 2; njp++)
#pragma unroll
            for (int h = 0; h < 2; h++) {
                float* c = acc[njp * 2 + h];
                MMA16816(c, ah, bh[njp][2 * h], bh[njp][2 * h + 1]);
                MMA16816(c, ah, bl[njp][2 * h], bl[njp][2 * h + 1]);
                MMA16816(c, al, bh[njp][2 * h], bh[njp][2 * h + 1]);
            }
    }
}

// ============================================================
// compute64: 128x64 tile, one K=64 chunk. 8 warps = 4m x 2n. (v2-verified)
// ============================================================
__device__ __forceinline__ void compute64(uint buf, float acc[2][4][4])
{
    const int lane = threadIdx.x & 31;
    const int w = threadIdx.x >> 5;
    const int m0w = (w & 3) * 32;
    const int n0w = (w >> 2) * 32;
    const int arow_l = lane & 15;
    const int au_l   = lane >> 4;
    const int brow_l = (lane & 7) + ((lane >> 4) & 1) * 8;
    const int bu_l   = (lane >> 3) & 1;
#pragma unroll
    for (int ks = 0; ks < 4; ks++) {
        uint ah[2][4], al[2][4], bh[2][4], bl[2][4];
#pragma unroll
        for (int mi = 0; mi < 2; mi++) {
            const int r = m0w + mi * 16 + arow_l;
            const int u = ks * 2 + au_l;
            const uint ad = buf + (uint)r * 128 + (uint)((u ^ (r & 7)) * 16);
            LDM4(ah[mi], ad);
            LDM4(al[mi], ad + BUF_AL);
        }
#pragma unroll
        for (int njp = 0; njp < 2; njp++) {
            const int r = n0w + njp * 16 + brow_l;
            const int u = ks * 2 + bu_l;
            const uint bd = buf + BUF_BH + (uint)r * 128 + (uint)((u ^ (r & 7)) * 16);
            LDM4(bh[njp], bd);
            LDM4(bl[njp], bd + (BUF_BL - BUF_BH));
        }
#pragma unroll
        for (int mi = 0; mi < 2; mi++)
#pragma unroll
            for (int njp = 0; njp < 2; njp++)
#pragma unroll
                for (int h = 0; h < 2; h++) {
                    float* c = acc[mi][njp * 2 + h];
                    MMA16816(c, ah[mi], bh[njp][2 * h], bh[njp][2 * h + 1]);
                    MMA16816(c, ah[mi], bl[njp][2 * h], bl[njp][2 * h + 1]);
                    MMA16816(c, al[mi], bh[njp][2 * h], bh[njp][2 * h + 1]);
                }
    }
}

// ============================================================
// P1 unit: H[z][:, n*32..+32] = tanh(x @ W1rows^T + b1), K=256 (4 chunks)
// x, W1 read as fp32 and split in-register. 1 sync per chunk.
// Publishes readiness flag g_rdy[z*8 + (n>>2)] on completion.
// ============================================================
__device__ void p1_unit(char* smem, uint sb, int z, int n,
                        const float* __restrict__ x,
                        const float* __restrict__ W1full,
                        const float* __restrict__ b1)
{
    const int tid = threadIdx.x;
    const int lane = tid & 31, w = tid >> 5;
    const float* W = W1full + (size_t)n * 32 * NDIM;
    char* cbuf[2] = {smem, smem + BUF_SZ};
    const uint bufs[2] = {sb, sb + BUF_SZ};

    const int ar  = tid >> 4;
    const int ak4 = (tid & 15) * 4;
    const int au  = (tid & 15) >> 1;
    const int ah8 = (tid & 1) * 8;

    float4 ax[8]; float4 bw[2];

    auto ldgs = [&](int kc) {
#pragma unroll
        for (int i = 0; i < 8; i++)
            ax[i] = *reinterpret_cast<const float4*>(
                &x[(size_t)(i * 16 + ar) * NDIM + kc + ak4]);
#pragma unroll
        for (int i = 0; i < 2; i++) {
            const int idx = i * 256 + tid;
            bw[i] = *reinterpret_cast<const float4*>(
                &W[(size_t)(idx >> 4) * NDIM + kc + (idx & 15) * 4]);
        }
    };
    auto sts = [&](char* b) {
#pragma unroll
        for (int i = 0; i < 8; i++) {
            const int row = i * 16 + ar;
            const uint off = (uint)row * 128 + (uint)((au ^ (row & 7)) * 16) + ah8;
            uint2 hu, lu; split4(ax[i], hu, lu);
            *reinterpret_cast<uint2*>(b + off)         = hu;
            *reinterpret_cast<uint2*>(b + P1_AL + off) = lu;
        }
#pragma unroll
        for (int i = 0; i < 2; i++) {
            const int idx = i * 256 + tid;
            const int row = idx >> 4;
            const int u = (idx & 15) >> 1, h8 = (idx & 1) * 8;
            const uint off = (uint)row * 128 + (uint)((u ^ (row & 7)) * 16) + h8;
            uint2 hu, lu; split4(bw[i], hu, lu);
            *reinterpret_cast<uint2*>(b + P1_BH + off) = hu;
            *reinterpret_cast<uint2*>(b + P1_BL + off) = lu;
        }
    };

    float acc[4][4];
#pragma unroll
    for (int a = 0; a < 4; a++)
#pragma unroll
        for (int q = 0; q < 4; q++) acc[a][q] = 0.f;

    ldgs(0);
    sts(cbuf[0]);
    ldgs(64);
    __syncthreads();
#pragma unroll
    for (int c = 0; c < 4; c++) {
        compute32(bufs[c & 1], acc);
        if (c < 3) {
            sts(cbuf[(c + 1) & 1]);           // other buffer: safe (sync'd last iter)
            if (c < 2) ldgs((c + 2) * 64);
            __syncthreads();
        }
    }

    // epilogue: tanh + hi/lo split -> g_Hh/g_Hl
    const int g = lane >> 2, t4 = lane & 3;
    const int row = w * 16 + g;
#pragma unroll
    for (int nj = 0; nj < 4; nj++) {
        const int col = n * 32 + nj * 8 + t4 * 2;
        float h0 = ftanh(acc[nj][0] + b1[col]);
        float h1 = ftanh(acc[nj][1] + b1[col + 1]);
        __nv_bfloat16 p0, q0, p1, q1;
        split_bf16(h0, p0, q0); split_bf16(h1, p1, q1);
        st_bf2(&g_Hh[z][(size_t)row * HDIM + col], p0, p1);
        st_bf2(&g_Hl[z][(size_t)row * HDIM + col], q0, q1);
        float h2 = ftanh(acc[nj][2] + b1[col]);
        float h3 = ftanh(acc[nj][3] + b1[col + 1]);
        split_bf16(h2, p0, q0); split_bf16(h3, p1, q1);
        st_bf2(&g_Hh[z][(size_t)(row + 8) * HDIM + col], p0, p1);
        st_bf2(&g_Hl[z][(size_t)(row + 8) * HDIM + col], q0, q1);
    }

    // publish readiness (release)
    __threadfence();
    __syncthreads();
    if (tid == 0) atomicAdd(&g_rdy[z * 8 + (n >> 2)], 1);
}

// ============================================================
// P2 unit: P2p[z][s] cols n*64..+64 = H[z][:, s*128..+128] @ W2 rows^T.
// W2 B-tiles preloaded into smem BEFORE waiting on producer flags.
// ============================================================
__device__ void p2_unit(char* smem, uint sb, int z, int n, int s,
                        const float* __restrict__ W2full)
{
    const int tid = threadIdx.x;
    const int lane = tid & 31, w = tid >> 5;
    const int k0 = s * 128;
    const __nv_bfloat16* Ah = g_Hh[z];
    const __nv_bfloat16* Al = g_Hl[z];
    const float* W = W2full + (size_t)n * 64 * HDIM;
    char* cbuf[2] = {smem, smem + BUF_SZ};
    const uint bufs[2] = {sb, sb + BUF_SZ};

    // ---- preload B (both chunks) while P1 is still running ----
#pragma unroll
    for (int ch = 0; ch < 2; ch++) {
        float4 bw[4];
#pragma unroll
        for (int i = 0; i < 4; i++) {
            const int idx = i * 256 + tid;
            bw[i] = *reinterpret_cast<const float4*>(
                &W[(size_t)(idx >> 4) * HDIM + k0 + ch * 64 + (idx & 15) * 4]);
        }
#pragma unroll
        for (int i = 0; i < 4; i++) {
            const int idx = i * 256 + tid;
            const int row = idx >> 4;
            const int u = (idx & 15) >> 1, h8 = (idx & 1) * 8;
            const uint off = (uint)row * 128 + (uint)((u ^ (row & 7)) * 16) + h8;
            uint2 hu, lu; split4(bw[i], hu, lu);
            *reinterpret_cast<uint2*>(cbuf[ch] + BUF_BH + off) = hu;
            *reinterpret_cast<uint2*>(cbuf[ch] + BUF_BL + off) = lu;
        }
    }

    // ---- wait for the 4 producer P1 units of (z, s)  (acquire) ----
    if (tid == 0) {
        while (atomicAdd(&g_rdy[z * 8 + s], 0) < 4) __nanosleep(64);
        __threadfence();
    }
    __syncthreads();

    // ---- cp.async the H A-tiles (both chunks) ----
    auto cpA = [&](uint b, int kc) {
#pragma unroll
        for (int i = 0; i < 4; i++) {
            const int idx = i * 256 + tid;
            const int row = idx >> 3, u = idx & 7;
            const uint off = (uint)row * 128 + (uint)((u ^ (row & 7)) * 16);
            CP16(b + off,          Ah + (size_t)row * HDIM + kc + u * 8);
            CP16(b + BUF_AL + off, Al + (size_t)row * HDIM + kc + u * 8);
        }
        CP_COMMIT();
    };
    cpA(bufs[0], k0);
    cpA(bufs[1], k0 + 64);

    float acc[2][4][4];
#pragma unroll
    for (int a = 0; a < 2; a++)
#pragma unroll
        for (int bq = 0; bq < 4; bq++)
#pragma unroll
            for (int q = 0; q < 4; q++) acc[a][bq][q] = 0.f;

    CP_WAIT(1);
    __syncthreads();
    compute64(bufs[0], acc);
    CP_WAIT(0);
    __syncthreads();
    compute64(bufs[1], acc);

    // ---- store fp32 partial ----
    float* O = g_P2p[z][s] + n * 64;
    const int g = lane >> 2, t4 = lane & 3;
    const int m0w = (w & 3) * 32, n0w = (w >> 2) * 32;
#pragma unroll
    for (int mi = 0; mi < 2; mi++)
#pragma unroll
        for (int nj = 0; nj < 4; nj++) {
            const int r = m0w + mi * 16 + g, c = n0w + nj * 8 + t4 * 2;
            *reinterpret_cast<float2*>(&O[(size_t)r * NDIM + c]) =
                make_float2(acc[mi][nj][0], acc[mi][nj][1]);
            *reinterpret_cast<float2*>(&O[(size_t)(r + 8) * NDIM + c]) =
                make_float2(acc[mi][nj][2], acc[mi][nj][3]);
        }
}

// ================= fallback machinery (verified; certified-unused) =============
struct Job {
    const __nv_bfloat16 *Ah, *Al, *Bh, *Bl;
    int lda, ldb, k0, nch, ldo;
    float* Of;
};
__device__ __forceinline__ void fill_chunk(uint buf, const Job& j, int kc)
{
    const int tid = threadIdx.x;
#pragma unroll
    for (int i = 0; i < 4; i++) {
        const int idx = tid + i * 256;
        const int row = idx >> 3, u = idx & 7;
        const uint sw = (uint)row * 128 + (uint)((u ^ (row & 7)) * 16);
        const size_t go = (size_t)row * j.lda + kc + u * 8;
        CP16(buf + sw,          j.Ah + go);
        CP16(buf + BUF_AL + sw, j.Al + go);
    }
#pragma unroll
    for (int i = 0; i < 2; i++) {
        const int idx = tid + i * 256;
        const int row = idx >> 3, u = idx & 7;
        const uint sw = (uint)row * 128 + (uint)((u ^ (row & 7)) * 16);
        const size_t go = (size_t)row * j.ldb + kc + u * 8;
        CP16(buf + BUF_BH + sw, j.Bh + go);
        CP16(buf + BUF_BL + sw, j.Bl + go);
    }
    CP_COMMIT();
}
__device__ __forceinline__ void store_tile(const Job& j, const float acc[2][4][4])
{
    const int lane = threadIdx.x & 31;
    const int w = threadIdx.x >> 5;
    const int g = lane >> 2, t = lane & 3;
    const int m0w = (w & 3) * 32, n0w = (w >> 2) * 32;
#pragma unroll
    for (int mi = 0; mi < 2; mi++)
#pragma unroll
        for (int nj = 0; nj < 4; nj++) {
            const int r = m0w + mi * 16 + g, c = n0w + nj * 8 + t * 2;
            *reinterpret_cast<float2*>(&j.Of[(size_t)r * j.ldo + c]) =
                make_float2(acc[mi][nj][0], acc[mi][nj][1]);
            *reinterpret_cast<float2*>(&j.Of[(size_t)(r + 8) * j.ldo + c]) =
                make_float2(acc[mi][nj][2], acc[mi][nj][3]);
        }
}
template <class DEC>
__device__ void gemm_phase(uint sb, int U, const DEC& dec)
{
    const uint buf0 = sb, buf1 = sb + BUF_SZ;
    for (int u = blockIdx.x; u < U; u += gridDim.x) {
        Job j; dec(u, j);
        fill_chunk(buf0, j, j.k0);
        fill_chunk(buf1, j, j.k0 + 64);
        float acc[2][4][4];
#pragma unroll
        for (int a = 0; a < 2; a++)
#pragma unroll
            for (int b = 0; b < 4; b++)
#pragma unroll
                for (int q = 0; q < 4; q++) acc[a][b][q] = 0.f;
        for (int c = 0; c < j.nch; c++) {
            if (c == j.nch - 1) { CP_WAIT(0); } else { CP_WAIT(1); }
            __syncthreads();
            compute64((c & 1) ? buf1 : buf0, acc);
            __syncthreads();
            if (c + 2 < j.nch)
                fill_chunk((c & 1) ? buf1 : buf0, j, j.k0 + (c + 2) * 64);
        }
        store_tile(j, acc);
        __syncthreads();
    }
}
struct DecP3 {
    __device__ void operator()(int u, Job& j) const {
        const int z = u >> 5, r = u & 31, n = r >> 1, s = r & 1;
        j.Ah = g_fgh[z]; j.Al = g_fgl[z]; j.lda = NDIM;
        j.Bh = g_K2Th + (size_t)n * 64 * NDIM;
        j.Bl = g_K2Tl + (size_t)n * 64 * NDIM; j.ldb = NDIM;
        j.k0 = s * 128; j.nch = 2;
        j.Of = g_P3p[z][s] + n * 64; j.ldo = HDIM;
    }
};
struct DecP4 {
    __device__ void operator()(int u, Job& j) const {
        const int z = u >> 5, r = u & 31, n = r >> 3, s = r & 7;
        j.Ah = g_dvh[z]; j.Al = g_dvl[z]; j.lda = HDIM;
        j.Bh = g_K1Th + (size_t)n * 64 * HDIM;
        j.Bl = g_K1Tl + (size_t)n * 64 * HDIM; j.ldb = HDIM;
        j.k0 = s * 128; j.nch = 2;
        j.Of = g_P4p[z][s] + n * 64; j.ldo = NDIM;
    }
};
__device__ void fnorm_block(const float* __restrict__ W, float* slot, float* red)
{
    float s = 0.f;
    for (int i = threadIdx.x; i < 2048; i += 256) {
        float4 v = reinterpret_cast<const float4*>(W)[i];
        s += v.x * v.x + v.y * v.y + v.z * v.z + v.w * v.w;
    }
#pragma unroll
    for (int off = 16; off > 0; off >>= 1) s += __shfl_down_sync(0xffffffffu, s, off);
    const int warp = threadIdx.x >> 5, lane = threadIdx.x & 31;
    if (lane == 0) red[warp] = s;
    __syncthreads();
    if (threadIdx.x == 0) {
        float t = 0.f;
#pragma unroll
        for (int ww = 0; ww < 8; ww++) t += red[ww];
        *slot = t;
    }
    __syncthreads();
}
__device__ void trans_tile(float (*ts)[65], const float* __restrict__ src, int lds,
                           int r0, int c0, __nv_bfloat16* dh, __nv_bfloat16* dl, int ldd)
{
    const int tid = threadIdx.x;
    __syncthreads();
    for (int i = tid; i < 4096; i += 256) {
        const int r = i >> 6, c = i & 63;
        ts[r][c] = src[(size_t)(r0 + r) * lds + c0 + c];
    }
    __syncthreads();
    for (int i = tid; i < 4096; i += 256) {
        const int dr = i >> 6, dc = i & 63;
        __nv_bfloat16 h, l;
        split_bf16(ts[dc][dr], h, l);
        dh[(size_t)(c0 + dr) * ldd + r0 + dc] = h;
        dl[(size_t)(c0 + dr) * ldd + r0 + dc] = l;
    }
}

// ---------------- persistent fused kernel ----------------
__global__ __launch_bounds__(256, 2) void fused_v5_kernel(
    const float* __restrict__ x,
    const float* __restrict__ Wf1, const float* __restrict__ bf1,
    const float* __restrict__ Wf2, const float* __restrict__ bf2,
    const float* __restrict__ Wg1, const float* __restrict__ bg1,
    const float* __restrict__ Wg2, const float* __restrict__ bg2,
    const float* __restrict__ Wk1, const float* __restrict__ bk1,
    const float* __restrict__ Wk2, const float* __restrict__ bk2,
    float* __restrict__ out)
{
    extern __shared__ char smem[];
    const uint sb = smem_u32(smem);
    float* red = reinterpret_cast<float*>(smem);
    const int tid = threadIdx.x;
    const int bid = blockIdx.x;
    const int gtid = bid * 256 + tid;
    const int gsz = gridDim.x * 256;

    // ---------- Region: P1 (0..95) || P2 (96..191, flag-synced) || fnorm ----------
    if (bid < 96) {
        const int z = bid >> 5, n = bid & 31;
        const float* W1 = (z == 0) ? Wf1 : (z == 1) ? Wg1 : Wk1;
        const float* b1 = (z == 0) ? bf1 : (z == 1) ? bg1 : bk1;
        p1_unit(smem, sb, z, n, x, W1, b1);
    } else if (bid < 192) {
        const int u = bid - 96;
        const int z = u >> 5, r = u & 31, n = r >> 3, s = r & 7;
        const float* W2 = (z == 0) ? Wf2 : (z == 1) ? Wg2 : Wk2;
        p2_unit(smem, sb, z, n, s, W2);
    } else if (bid < 256) {
        const int jb = bid - 192;
        if (jb < 32) fnorm_block(Wk1 + (size_t)jb * 8192, &g_F1p[jb], red);
        else         fnorm_block(Wk2 + (size_t)(jb - 32) * 8192, &g_F2p[jb - 32], red);
    }
    gbar();

    // ---------- Phase C: fgk, speculative out, certification; reset flags ----------
    if (bid < BSZ) {
        const int b = bid, i = tid;
        const int idx = b * NDIM + i;
        float fv = bf2[i], gv = bg2[i], kv = bk2[i];
#pragma unroll
        for (int s = 0; s < 8; s++) {
            fv += g_P2p[0][s][idx];
            gv += g_P2p[1][s][idx];
            kv += g_P2p[2][s][idx];
        }
        g_fgk[0][idx] = fv; g_fgk[1][idx] = gv; g_fgk[2][idx] = kv;
        out[idx] = 0.5f * (fv + gv);          // speculative (certified below)

        float kn2 = kv * kv, gn2 = gv * gv;
#pragma unroll
        for (int off = 16; off > 0; off >>= 1) {
            kn2 += __shfl_down_sync(0xffffffffu, kn2, off);
            gn2 += __shfl_down_sync(0xffffffffu, gn2, off);
        }
        const int warp = i >> 5, lane = i & 31;
        if (lane == 0) { red[warp] = kn2; red[8 + warp] = gn2; }
        __syncthreads();
        if (i == 0) {
            float tkn2 = 0.f, tgn2 = 0.f;
#pragma unroll
            for (int ww = 0; ww < 8; ww++) { tkn2 += red[ww]; tgn2 += red[8 + ww]; }
            float F1sq = 0.f, F2sq = 0.f;
#pragma unroll
            for (int p = 0; p < 32; p++) { F1sq += g_F1p[p]; F2sq += g_F2p[p]; }
            const float F  = sqrtf(F1sq) * sqrtf(F2sq);
            const float kn = sqrtf(tkn2), gn = sqrtf(tgn2);
            const float kn10 = tkn2 * tkn2 * tkn2 * tkn2 * tkn2;
            const int certified = (BETA * kn10 > 2.0f * kn * F * gn + 1.0f);
            g_bad[b] = certified ? 0 : 1;
        }
        __syncthreads();
    } else if (bid == 128) {
        if (tid < 24) g_rdy[tid] = 0;        // reset producer flags for next replay
    }
    gbar();

    // ---------- decision (uniform across grid) ----------
    {
        int bad = (tid < BSZ) ? g_bad[tid] : 0;
        if (__syncthreads_or(bad) == 0) return;   // fast path done
    }

    // ================= FALLBACK (certified-impossible, but exact) =================
    for (int i = gtid; i < BSZ * HDIM; i += gsz) {
        const float t = __bfloat162float(g_Hh[2][i]) + __bfloat162float(g_Hl[2][i]);
        g_D[i] = 1.0f - t * t;
    }
    for (int i = gtid; i < 2 * BSZ * NDIM; i += gsz) {
        const int z = i / (BSZ * NDIM), j = i - z * (BSZ * NDIM);
        __nv_bfloat16 h, l;
        split_bf16(g_fgk[z][j], h, l);
        g_fgh[z][j] = h; g_fgl[z][j] = l;
    }
    {
        float (*ts)[65] = reinterpret_cast<float(*)[65]>(smem);
        for (int t = bid; t < 128; t += gridDim.x) {
            if (t < 64)
                trans_tile(ts, Wk1, NDIM, (t >> 2) * 64, (t & 3) * 64, g_K1Th, g_K1Tl, HDIM);
            else {
                const int tt = t - 64;
                trans_tile(ts, Wk2, HDIM, (tt & 3) * 64, (tt >> 2) * 64, g_K2Th, g_K2Tl, NDIM);
            }
        }
    }
    gbar();
    gemm_phase(sb, 64, DecP3{});
    gbar();
    for (int i = gtid; i < 2 * BSZ * HDIM; i += gsz) {
        const int z = i / (BSZ * HDIM), j = i - z * (BSZ * HDIM);
        const float v = (g_P3p[z][0][j] + g_P3p[z][1][j]) * g_D[j];
        __nv_bfloat16 h, l;
        split_bf16(v, h, l);
        g_dvh[z][j] = h; g_dvl[z][j] = l;
    }
    gbar();
    gemm_phase(sb, 64, DecP4{});
    gbar();
    if (bid < BSZ) {
        const int b = bid, i = tid;
        const int idx = b * NDIM + i;
        float jfv = 0.f, jgv = 0.f;
#pragma unroll
        for (int s = 0; s < 8; s++) {
            jfv += g_P4p[0][s][idx];
            jgv += g_P4p[1][s][idx];
        }
        const float fv = g_fgk[0][idx];
        const float gv = g_fgk[1][idx];
        const float kv = g_fgk[2][idx];
        float kn2 = kv * kv, jf2 = jfv * jfv, dt = kv * jgv;
#pragma unroll
        for (int off = 16; off > 0; off >>= 1) {
            kn2 += __shfl_down_sync(0xffffffffu, kn2, off);
            jf2 += __shfl_down_sync(0xffffffffu, jf2, off);
            dt  += __shfl_down_sync(0xffffffffu, dt,  off);
        }
        const int warp = i >> 5, lane = i & 31;
        if (lane == 0) { red[warp] = kn2; red[8 + warp] = jf2; red[16 + warp] = dt; }
        __syncthreads();
        __shared__ float s_scale;
        if (i == 0) {
            float tkn2 = 0.f, tjf2 = 0.f, tdt = 0.f;
#pragma unroll
            for (int ww = 0; ww < 8; ww++) {
                tkn2 += red[ww]; tjf2 += red[8 + ww]; tdt += red[16 + ww];
            }
            const float kn   = sqrtf(tkn2);
            const float kn9  = tkn2 * tkn2 * tkn2 * tkn2 * kn;
            const float kn10 = kn9 * kn;
            const float c1 = sqrtf(tjf2) - ALPHA * kn9;
            const float c2 = tdt - BETA * kn10;
            s_scale = ((c1 > EPSC) || (c2 < -EPSC)) ? 0.5f : 1.0f;
        }
        __syncthreads();
        out[idx] = s_scale * (fv + gv);
    }
}

// inputs: 0:t 1:x 2:Wf1 3:bf1 4:Wf2 5:bf2 6:Wg1 7:bg1 8:Wg2 9:bg2 10:Wk1 11:bk1 12:Wk2 13:bk2
extern "C" void kernel_launch(void* const* d_in, const int* in_sizes, int n_in,
                              void* d_out, int out_size)
{
    const float* x   = (const float*)d_in[1];
    const float* Wf1 = (const float*)d_in[2];
    const float* bf1 = (const float*)d_in[3];
    const float* Wf2 = (const float*)d_in[4];
    const float* bf2 = (const float*)d_in[5];
    const float* Wg1 = (const float*)d_in[6];
    const float* bg1 = (const float*)d_in[7];
    const float* Wg2 = (const float*)d_in[8];
    const float* bg2 = (const float*)d_in[9];
    const float* Wk1 = (const float*)d_in[10];
    const float* bk1 = (const float*)d_in[11];
    const float* Wk2 = (const float*)d_in[12];
    const float* bk2 = (const float*)d_in[13];
    float* out = (float*)d_out;

    cudaFuncSetAttribute(fused_v5_kernel,
                         cudaFuncAttributeMaxDynamicSharedMemorySize, SMEM_TOTAL);

    int dev = 0, sms = 148;
    cudaGetDevice(&dev);
    cudaDeviceGetAttribute(&sms, cudaDevAttrMultiProcessorCount, dev);
    int occ = 1;
    cudaOccupancyMaxActiveBlocksPerMultiprocessor(&occ, fused_v5_kernel, 256, SMEM_TOTAL);
    if (occ < 1) occ = 1;
    if (occ > 2) occ = 2;
    int grid = sms * occ;
    if (grid < 256) grid = 256;   // region needs blocks up to 255 co-resident

    fused_v5_kernel<<<grid, 256, SMEM_TOTAL>>>(x, Wf1, bf1, Wf2, bf2, Wg1, bg1,
                                               Wg2, bg2, Wk1, bk1, Wk2, bk2, out);
}